// round 9
// baseline (speedup 1.0000x reference)
#include <cuda_runtime.h>
#include <cstdint>

// Shapes (fixed by the problem)
#define BB   4
#define TT   512
#define FF   93
#define DSS  64
#define DD   1024
#define HH   8
#define MM   (BB*TT)      // 2048 rows

// Scratch (static device allocations; no cudaMalloc allowed)
__device__ float    g_y0pre[MM*DSS];      // spectral fct output pre-Wos  [2048,64]
__device__ float    g_WosWt[DSS*DD];      // Wos @ Wt                     [64,1024]
__device__ uint32_t g_xt32[MM*DD];        // temporal input, tf32 bits (plain [m][k])
__device__ uint32_t g_w32[4*DD*DD];       // Wq,Wk,Wv,Wo tf32 bits (plain [k][n])
__device__ uint32_t g_qkv32[3*MM*DD];     // Q,K,V as tf32 bit patterns
__device__ uint32_t g_attnout32[MM*DD];   // attention out, tf32 bits (plain [m][k])

// ---------------------------------------------------------------------------
// helpers: tf32 convert + mma
// ---------------------------------------------------------------------------
__device__ __forceinline__ uint32_t f2tf32(float x) {
    uint32_t r;
    asm("cvt.rna.tf32.f32 %0, %1;" : "=r"(r) : "f"(x));
    return r;
}
__device__ __forceinline__ void mma_tf32(float c[4], const uint32_t a[4], const uint32_t b[2]) {
    asm volatile(
        "mma.sync.aligned.m16n8k8.row.col.f32.tf32.tf32.f32 "
        "{%0,%1,%2,%3}, {%4,%5,%6,%7}, {%8,%9}, {%0,%1,%2,%3};"
        : "+f"(c[0]), "+f"(c[1]), "+f"(c[2]), "+f"(c[3])
        : "r"(a[0]), "r"(a[1]), "r"(a[2]), "r"(a[3]), "r"(b[0]), "r"(b[1]));
}

// ---------------------------------------------------------------------------
// prep: convert weights (same [k][n] layout) to tf32 bits. 4 elems/thread.
// grid (1024, 4), block 256
// ---------------------------------------------------------------------------
__global__ void prep_w_kernel(const float* __restrict__ Wq,
                              const float* __restrict__ Wk,
                              const float* __restrict__ Wv,
                              const float* __restrict__ Wo) {
    const int z = blockIdx.y;
    const float* S = (z == 0) ? Wq : (z == 1) ? Wk : (z == 2) ? Wv : Wo;
    int i = (blockIdx.x * 256 + threadIdx.x) * 4;
    float4 v = *(const float4*)(S + i);
    *(uint4*)(g_w32 + (size_t)z * DD * DD + i) =
        make_uint4(f2tf32(v.x), f2tf32(v.y), f2tf32(v.z), f2tf32(v.w));
}

// ---------------------------------------------------------------------------
// WosWt = Wos[64,64] @ Wt[64,1024]
// ---------------------------------------------------------------------------
__global__ void woswt_kernel(const float* __restrict__ Wos, const float* __restrict__ Wt) {
    int idx = blockIdx.x * 256 + threadIdx.x;   // 65536 outputs
    int r = idx >> 10, c = idx & 1023;
    float s = 0.f;
    #pragma unroll 8
    for (int k = 0; k < 64; k++) s += Wos[r*64 + k] * Wt[k*1024 + c];
    g_WosWt[idx] = s;
}

// ---------------------------------------------------------------------------
// Spectral attention, fct query only (row-0 mask is all-True).
// ---------------------------------------------------------------------------
__global__ void spectral_kernel(const float* __restrict__ xs,
                                const float* __restrict__ Wqs,
                                const float* __restrict__ Wks,
                                const float* __restrict__ Wvs) {
    __shared__ float xs_s[FF*68];
    __shared__ float q0_s[64];
    __shared__ float qW_s[8*64];
    __shared__ float p_s[8*96];
    __shared__ float a_s[8*64];

    const int bt  = blockIdx.x;
    const int tid = threadIdx.x;   // 256
    const float* xp = xs + (size_t)bt * FF * DSS;

    for (int idx = tid; idx < FF*DSS; idx += 256)
        xs_s[(idx >> 6) * 68 + (idx & 63)] = xp[idx];
    __syncthreads();

    if (tid < 64) {
        float s = 0.f;
        #pragma unroll 8
        for (int k = 0; k < 64; k++) s += xs_s[k] * __ldg(&Wqs[k*64 + tid]);
        q0_s[tid] = s;
    }
    __syncthreads();

    for (int idx = tid; idx < 512; idx += 256) {
        int h = idx >> 6, k = idx & 63;
        float s = 0.f;
        #pragma unroll
        for (int d = 0; d < 8; d++) s += q0_s[h*8 + d] * __ldg(&Wks[k*64 + h*8 + d]);
        qW_s[idx] = s;
    }
    __syncthreads();

    const float scale = 0.35355339059327376f;   // 1/sqrt(8)
    for (int idx = tid; idx < 8*FF; idx += 256) {
        int h = idx / FF, j = idx - h * FF;
        const float* xr = &xs_s[j*68];
        const float* qr = &qW_s[h*64];
        float s = 0.f;
        #pragma unroll
        for (int k4 = 0; k4 < 16; k4++) {
            float4 a = *(const float4*)(xr + k4*4);
            float4 w = *(const float4*)(qr + k4*4);
            s += a.x*w.x + a.y*w.y + a.z*w.z + a.w*w.w;
        }
        p_s[h*96 + j] = s * scale;
    }
    __syncthreads();

    {
        int w = tid >> 5, lane = tid & 31;
        float m = -3.0e38f;
        for (int j = lane; j < FF; j += 32) m = fmaxf(m, p_s[w*96 + j]);
        #pragma unroll
        for (int o = 16; o > 0; o >>= 1) m = fmaxf(m, __shfl_xor_sync(0xffffffffu, m, o));
        float sum = 0.f;
        for (int j = lane; j < FF; j += 32) {
            float e = __expf(p_s[w*96 + j] - m);
            p_s[w*96 + j] = e; sum += e;
        }
        #pragma unroll
        for (int o = 16; o > 0; o >>= 1) sum += __shfl_xor_sync(0xffffffffu, sum, o);
        float inv = 1.f / sum;
        for (int j = lane; j < FF; j += 32) p_s[w*96 + j] *= inv;
    }
    __syncthreads();

    for (int idx = tid; idx < 512; idx += 256) {
        int h = idx >> 6, k = idx & 63;
        float s = 0.f;
        for (int j = 0; j < FF; j++) s += p_s[h*96 + j] * xs_s[j*68 + k];
        a_s[idx] = s;
    }
    __syncthreads();

    if (tid < 64) {
        int h = tid >> 3;
        float s = 0.f;
        #pragma unroll 8
        for (int k = 0; k < 64; k++) s += a_s[h*64 + k] * __ldg(&Wvs[k*64 + tid]);
        g_y0pre[bt*64 + tid] = s;
    }
}

// ---------------------------------------------------------------------------
// xt = x + y0pre @ WosWt -> tf32 bits (plain layout).
// 512 threads, float2 columns (low reg pressure, higher occupancy).
// ---------------------------------------------------------------------------
__global__ void __launch_bounds__(512) xt_kernel(const float* __restrict__ x) {
    const int r0  = blockIdx.x * 16;
    const int tid = threadIdx.x;     // 512
    __shared__ float y0[16][64];

    for (int idx = tid; idx < 16*64; idx += 512)
        y0[idx >> 6][idx & 63] = g_y0pre[(r0 + (idx >> 6)) * 64 + (idx & 63)];
    __syncthreads();

    const int c = tid * 2;
    float2 acc[16];
    #pragma unroll
    for (int r = 0; r < 16; r++)
        acc[r] = *(const float2*)(x + (size_t)(r0 + r) * DD + c);

    #pragma unroll 4
    for (int k = 0; k < 64; k++) {
        float2 w = *(const float2*)(g_WosWt + k * DD + c);
        #pragma unroll
        for (int r = 0; r < 16; r++) {
            float y = y0[r][k];
            acc[r].x += y * w.x; acc[r].y += y * w.y;
        }
    }
    #pragma unroll
    for (int r = 0; r < 16; r++)
        *(uint2*)(g_xt32 + (size_t)(r0 + r) * DD + c) =
            make_uint2(f2tf32(acc[r].x), f2tf32(acc[r].y));
}

// ---------------------------------------------------------------------------
// tf32 tensor-core GEMM, DOUBLE-BUFFERED smem, BK=16, one sync per k-tile.
// A,B pre-converted tf32 bits; block tile 128x128, 8 warps (4x2), warp 32x64.
// ---------------------------------------------------------------------------
template <bool CVT_OUT>
__device__ __forceinline__ void gemm_tf32_tile(const uint32_t* __restrict__ A32,
                                               const uint32_t* __restrict__ B32,
                                               void* __restrict__ Cv,
                                               int bm, int bn) {
    __shared__ uint32_t As[2][128][20];   // [stage][m][k] pad 20 (banks: 20g%32 = 4-spaced)
    __shared__ uint32_t Bs[2][16][132];   // [stage][k][n] pad 132 (banks: 4t+g)

    const int tid  = threadIdx.x;
    const int warp = tid >> 5, lane = tid & 31;
    const int wm = (warp >> 1) * 32;   // 4 warp-rows
    const int wn = (warp & 1) * 64;    // 2 warp-cols
    const int g = lane >> 2, t = lane & 3;

    const int aRow = tid >> 2,  aC = (tid & 3) << 2;   // A: 64 rows per i-step
    const int bRow = tid >> 5,  bC = (tid & 31) << 2;  // B: 8 rows per i-step

    uint4 pa[2], pb[2];
    auto loadT = [&](int k0) {
        #pragma unroll
        for (int i = 0; i < 2; i++) {
            pa[i] = *(const uint4*)(A32 + (size_t)(bm + aRow + 64*i) * 1024 + k0 + aC);
            pb[i] = *(const uint4*)(B32 + (size_t)(k0 + bRow + 8*i) * 1024 + bn + bC);
        }
    };
    auto storeT = [&](int s) {
        #pragma unroll
        for (int i = 0; i < 2; i++) {
            *(uint4*)&As[s][aRow + 64*i][aC] = pa[i];
            *(uint4*)&Bs[s][bRow + 8*i][bC] = pb[i];
        }
    };

    float acc[2][8][4];
    #pragma unroll
    for (int mi = 0; mi < 2; mi++)
        #pragma unroll
        for (int ni = 0; ni < 8; ni++)
            #pragma unroll
            for (int r = 0; r < 4; r++) acc[mi][ni][r] = 0.f;

    loadT(0); storeT(0);
    __syncthreads();

    #pragma unroll 2
    for (int kt = 0; kt < 64; kt++) {
        const int s = kt & 1;
        const bool more = (kt + 1) < 64;
        if (more) loadT((kt + 1) * 16);

        #pragma unroll
        for (int kk = 0; kk < 16; kk += 8) {
            uint32_t a[2][4], b[8][2];
            #pragma unroll
            for (int mi = 0; mi < 2; mi++) {
                int m = wm + mi * 16 + g;
                a[mi][0] = As[s][m    ][kk + t];
                a[mi][1] = As[s][m + 8][kk + t];
                a[mi][2] = As[s][m    ][kk + t + 4];
                a[mi][3] = As[s][m + 8][kk + t + 4];
            }
            #pragma unroll
            for (int ni = 0; ni < 8; ni++) {
                int n = wn + ni * 8 + g;
                b[ni][0] = Bs[s][kk + t    ][n];
                b[ni][1] = Bs[s][kk + t + 4][n];
            }
            #pragma unroll
            for (int mi = 0; mi < 2; mi++)
                #pragma unroll
                for (int ni = 0; ni < 8; ni++)
                    mma_tf32(acc[mi][ni], a[mi], b[ni]);
        }

        if (more) storeT(s ^ 1);   // stage s^1 was last READ in iter kt-1 (sealed by its sync)
        __syncthreads();
    }

    #pragma unroll
    for (int mi = 0; mi < 2; mi++) {
        int row0 = bm + wm + mi * 16 + g;
        #pragma unroll
        for (int ni = 0; ni < 8; ni++) {
            int col = bn + wn + ni * 8 + t * 2;
            if (CVT_OUT) {
                uint32_t* C = (uint32_t*)Cv;
                *(uint2*)(C + (size_t)row0 * 1024 + col) =
                    make_uint2(f2tf32(acc[mi][ni][0]), f2tf32(acc[mi][ni][1]));
                *(uint2*)(C + (size_t)(row0 + 8) * 1024 + col) =
                    make_uint2(f2tf32(acc[mi][ni][2]), f2tf32(acc[mi][ni][3]));
            } else {
                float* C = (float*)Cv;
                *(float2*)(C + (size_t)row0 * 1024 + col) =
                    make_float2(acc[mi][ni][0], acc[mi][ni][1]);
                *(float2*)(C + (size_t)(row0 + 8) * 1024 + col) =
                    make_float2(acc[mi][ni][2], acc[mi][ni][3]);
            }
        }
    }
}

__global__ void __launch_bounds__(256, 2) qkv_gemm_kernel() {
    int which = blockIdx.x >> 3;                // 0..2
    int bn    = (blockIdx.x & 7) * 128;
    int bm    = blockIdx.y * 128;
    const uint32_t* W = g_w32 + (size_t)which * DD * DD;
    uint32_t* C = g_qkv32 + (size_t)which * MM * DD;
    gemm_tf32_tile<true>(g_xt32, W, C, bm, bn);
}

__global__ void __launch_bounds__(256, 2) out_gemm_kernel(float* __restrict__ C) {
    gemm_tf32_tile<false>(g_attnout32, g_w32 + 3 * (size_t)DD * DD, C,
                          blockIdx.y * 128, blockIdx.x * 128);
}

// ---------------------------------------------------------------------------
// Temporal attention: block-diagonal flash on tf32 tensor cores.
// ---------------------------------------------------------------------------
__global__ void __launch_bounds__(256) temporal_attn_kernel(const int* __restrict__ valid_len) {
    __shared__ uint32_t Qs [32][132];
    __shared__ uint32_t KVs[32][132];
    __shared__ float    Ss [32][36];
    __shared__ float m_s[32], l_s[32], al_s[32];
    __shared__ int   lo_s[32], hi_s[32];

    const int qt = blockIdx.x, h = blockIdx.y, b = blockIdx.z;
    const int tid = threadIdx.x;
    const int warp = tid >> 5, lane = tid & 31;
    const int g = lane >> 2, t = lane & 3;
    const int q0 = qt * 32;
    const uint32_t* Q = g_qkv32;
    const uint32_t* K = g_qkv32 + (size_t)MM * DD;
    const uint32_t* V = g_qkv32 + 2 * (size_t)MM * DD;
    const int l = valid_len[b];

    if (tid < 32) {
        int i = q0 + tid;
        int lo, hi;
        const int dv = (h >> 1) + 1;
        if (i < l) {
            int c = (i * dv) / l;
            lo = (c * l + dv - 1) / dv;
            hi = ((c + 1) * l - 1) / dv + 1;
            if (hi > l) hi = l;
        } else { lo = l; hi = TT; }
        lo_s[tid] = lo; hi_s[tid] = hi;
        m_s[tid] = -1e30f; l_s[tid] = 0.f;
    }
    for (int f = tid; f < 32*32; f += 256) {
        int r = f >> 5, c4 = (f & 31) << 2;
        *(uint4*)&Qs[r][c4] =
            *(const uint4*)(Q + (size_t)(b*TT + q0 + r)*DD + h*128 + c4);
    }
    __syncthreads();
    const int bLo = lo_s[0], bHi = hi_s[31];   // lo/hi monotone in i

    const int wmS = (warp >> 2) * 16, wnS = (warp & 3) * 8;   // S: 16x8 per warp
    const int wmP = (warp >> 2) * 16, wnP = (warp & 3) * 32;  // PV: 16x32 per warp
    const float scale = 0.08838834764831845f;  // 1/sqrt(128)

    float O[4][4];
    #pragma unroll
    for (int ni = 0; ni < 4; ni++)
        #pragma unroll
        for (int r = 0; r < 4; r++) O[ni][r] = 0.f;

    for (int kt = bLo & ~31; kt < bHi; kt += 32) {
        for (int f = tid; f < 32*32; f += 256) {
            int r = f >> 5, c4 = (f & 31) << 2;
            int j = kt + r; if (j > TT - 1) j = TT - 1;
            *(uint4*)&KVs[r][c4] =
                *(const uint4*)(K + (size_t)(b*TT + j)*DD + h*128 + c4);
        }
        __syncthreads();

        float sc[4] = {0.f, 0.f, 0.f, 0.f};
        #pragma unroll
        for (int kk = 0; kk < 128; kk += 8) {
            uint32_t a[4], bb[2];
            a[0] = Qs[wmS + g    ][kk + t];
            a[1] = Qs[wmS + g + 8][kk + t];
            a[2] = Qs[wmS + g    ][kk + t + 4];
            a[3] = Qs[wmS + g + 8][kk + t + 4];
            bb[0] = KVs[wnS + g][kk + t];
            bb[1] = KVs[wnS + g][kk + t + 4];
            mma_tf32(sc, a, bb);
        }
        Ss[wmS + g    ][wnS + 2*t    ] = sc[0] * scale;
        Ss[wmS + g    ][wnS + 2*t + 1] = sc[1] * scale;
        Ss[wmS + g + 8][wnS + 2*t    ] = sc[2] * scale;
        Ss[wmS + g + 8][wnS + 2*t + 1] = sc[3] * scale;
        __syncthreads();

        if (tid < 32) {
            const int lo = lo_s[tid], hi = hi_s[tid];
            float mo = m_s[tid];
            float rmax = -3e38f;
            #pragma unroll 8
            for (int j = 0; j < 32; j++) {
                int jg = kt + j;
                float s = (jg >= lo && jg < hi) ? Ss[tid][j] : -3e38f;
                Ss[tid][j] = s;
                rmax = fmaxf(rmax, s);
            }
            float mn = fmaxf(mo, rmax);
            float alpha = __expf(mo - mn);
            float rs = 0.f;
            #pragma unroll 8
            for (int j = 0; j < 32; j++) {
                float p = __expf(Ss[tid][j] - mn);
                Ss[tid][j] = p;
                rs += p;
            }
            l_s[tid] = l_s[tid] * alpha + rs;
            m_s[tid] = mn;
            al_s[tid] = alpha;
        }
        for (int f = tid; f < 32*32; f += 256) {
            int r = f >> 5, c4 = (f & 31) << 2;
            int j = kt + r; if (j > TT - 1) j = TT - 1;
            *(uint4*)&KVs[r][c4] =
                *(const uint4*)(V + (size_t)(b*TT + j)*DD + h*128 + c4);
        }
        __syncthreads();

        {
            float a0 = al_s[wmP + g], a1 = al_s[wmP + g + 8];
            #pragma unroll
            for (int ni = 0; ni < 4; ni++) {
                O[ni][0] *= a0; O[ni][1] *= a0;
                O[ni][2] *= a1; O[ni][3] *= a1;
            }
        }
        #pragma unroll
        for (int kk = 0; kk < 32; kk += 8) {
            uint32_t a[4];
            a[0] = f2tf32(Ss[wmP + g    ][kk + t]);
            a[1] = f2tf32(Ss[wmP + g + 8][kk + t]);
            a[2] = f2tf32(Ss[wmP + g    ][kk + t + 4]);
            a[3] = f2tf32(Ss[wmP + g + 8][kk + t + 4]);
            #pragma unroll
            for (int ni = 0; ni < 4; ni++) {
                uint32_t bb[2];
                int n = wnP + ni * 8 + g;
                bb[0] = KVs[kk + t    ][n];
                bb[1] = KVs[kk + t + 4][n];
                mma_tf32(O[ni], a, bb);
            }
        }
        __syncthreads();
    }

    {
        float inv0 = 1.f / l_s[wmP + g];
        float inv1 = 1.f / l_s[wmP + g + 8];
        const size_t r0 = (size_t)(b*TT + q0 + wmP + g) * DD;
        const size_t r1 = (size_t)(b*TT + q0 + wmP + g + 8) * DD;
        #pragma unroll
        for (int ni = 0; ni < 4; ni++) {
            int col = h*128 + wnP + ni*8 + 2*t;
            *(uint2*)(g_attnout32 + r0 + col) =
                make_uint2(f2tf32(O[ni][0]*inv0), f2tf32(O[ni][1]*inv0));
            *(uint2*)(g_attnout32 + r1 + col) =
                make_uint2(f2tf32(O[ni][2]*inv1), f2tf32(O[ni][3]*inv1));
        }
    }
}

// ---------------------------------------------------------------------------
extern "C" void kernel_launch(void* const* d_in, const int* in_sizes, int n_in,
                              void* d_out, int out_size) {
    const float* x   = (const float*)d_in[0];
    const float* xs  = (const float*)d_in[1];
    const int*   vl  = (const int*)  d_in[2];
    const float* Wq  = (const float*)d_in[3];
    const float* Wk  = (const float*)d_in[4];
    const float* Wv  = (const float*)d_in[5];
    const float* Wo  = (const float*)d_in[6];
    const float* Wqs = (const float*)d_in[7];
    const float* Wks = (const float*)d_in[8];
    const float* Wvs = (const float*)d_in[9];
    const float* Wos = (const float*)d_in[10];
    const float* Wt  = (const float*)d_in[11];
    float* out = (float*)d_out;

    prep_w_kernel<<<dim3(1024, 4), 256>>>(Wq, Wk, Wv, Wo);
    woswt_kernel<<<256, 256>>>(Wos, Wt);
    spectral_kernel<<<MM, 256>>>(xs, Wqs, Wks, Wvs);
    xt_kernel<<<MM/16, 512>>>(x);
    qkv_gemm_kernel<<<dim3(24, 16), 256>>>();
    temporal_attn_kernel<<<dim3(TT/32, HH, BB), 256>>>(vl);
    out_gemm_kernel<<<dim3(8, 16), 256>>>(out);
}

// round 12
// speedup vs baseline: 1.0792x; 1.0792x over previous
#include <cuda_runtime.h>
#include <cstdint>

// Shapes (fixed by the problem)
#define BB   4
#define TT   512
#define FF   93
#define DSS  64
#define DD   1024
#define HH   8
#define MM   (BB*TT)      // 2048 rows

// Scratch (static device allocations; no cudaMalloc allowed)
__device__ float    g_y0pre[MM*DSS];      // spectral fct output pre-Wos  [2048,64]
__device__ float    g_WosWt[DSS*DD];      // Wos @ Wt                     [64,1024]
__device__ uint32_t g_xt32[MM*DD];        // temporal input, tf32 bits (plain [m][k])
__device__ uint32_t g_w32[4*DD*DD];       // Wq,Wk,Wv,Wo tf32 bits (plain [k][n])
__device__ uint32_t g_qkv32[3*MM*DD];     // Q,K,V as tf32 bit patterns
__device__ uint32_t g_attnout32[MM*DD];   // attention out, tf32 bits (plain [m][k])

// ---------------------------------------------------------------------------
// helpers: tf32 convert + mma
// ---------------------------------------------------------------------------
__device__ __forceinline__ uint32_t f2tf32(float x) {
    uint32_t r;
    asm("cvt.rna.tf32.f32 %0, %1;" : "=r"(r) : "f"(x));
    return r;
}
__device__ __forceinline__ void mma_tf32(float c[4], const uint32_t a[4], const uint32_t b[2]) {
    asm volatile(
        "mma.sync.aligned.m16n8k8.row.col.f32.tf32.tf32.f32 "
        "{%0,%1,%2,%3}, {%4,%5,%6,%7}, {%8,%9}, {%0,%1,%2,%3};"
        : "+f"(c[0]), "+f"(c[1]), "+f"(c[2]), "+f"(c[3])
        : "r"(a[0]), "r"(a[1]), "r"(a[2]), "r"(a[3]), "r"(b[0]), "r"(b[1]));
}

// ---------------------------------------------------------------------------
// prep: convert weights (same [k][n] layout) to tf32 bits. 4 elems/thread.
// grid (1024, 4), block 256
// ---------------------------------------------------------------------------
__global__ void prep_w_kernel(const float* __restrict__ Wq,
                              const float* __restrict__ Wk,
                              const float* __restrict__ Wv,
                              const float* __restrict__ Wo) {
    const int z = blockIdx.y;
    const float* S = (z == 0) ? Wq : (z == 1) ? Wk : (z == 2) ? Wv : Wo;
    int i = (blockIdx.x * 256 + threadIdx.x) * 4;
    float4 v = *(const float4*)(S + i);
    *(uint4*)(g_w32 + (size_t)z * DD * DD + i) =
        make_uint4(f2tf32(v.x), f2tf32(v.y), f2tf32(v.z), f2tf32(v.w));
}

// ---------------------------------------------------------------------------
// WosWt = Wos[64,64] @ Wt[64,1024]
// ---------------------------------------------------------------------------
__global__ void woswt_kernel(const float* __restrict__ Wos, const float* __restrict__ Wt) {
    int idx = blockIdx.x * 256 + threadIdx.x;   // 65536 outputs
    int r = idx >> 10, c = idx & 1023;
    float s = 0.f;
    #pragma unroll 8
    for (int k = 0; k < 64; k++) s += Wos[r*64 + k] * Wt[k*1024 + c];
    g_WosWt[idx] = s;
}

// ---------------------------------------------------------------------------
// Spectral attention, fct query only (row-0 mask is all-True).
// a-phase: 128 threads own (h, 4-wide k group), float4 xs reads.
// ---------------------------------------------------------------------------
__global__ void spectral_kernel(const float* __restrict__ xs,
                                const float* __restrict__ Wqs,
                                const float* __restrict__ Wks,
                                const float* __restrict__ Wvs) {
    __shared__ float xs_s[FF*68];
    __shared__ float q0_s[64];
    __shared__ float qW_s[8*64];
    __shared__ float p_s[8*96];
    __shared__ float a_s[8*64];

    const int bt  = blockIdx.x;
    const int tid = threadIdx.x;   // 256
    const float* xp = xs + (size_t)bt * FF * DSS;

    for (int idx = tid; idx < FF*DSS; idx += 256)
        xs_s[(idx >> 6) * 68 + (idx & 63)] = xp[idx];
    __syncthreads();

    if (tid < 64) {
        float s = 0.f;
        #pragma unroll 8
        for (int k = 0; k < 64; k++) s += xs_s[k] * __ldg(&Wqs[k*64 + tid]);
        q0_s[tid] = s;
    }
    __syncthreads();

    // qW[h][k] = sum_d q0[h*8+d] * Wks[k][h*8+d]
    for (int idx = tid; idx < 512; idx += 256) {
        int h = idx >> 6, k = idx & 63;
        float s = 0.f;
        #pragma unroll
        for (int d = 0; d < 8; d++) s += q0_s[h*8 + d] * __ldg(&Wks[k*64 + h*8 + d]);
        qW_s[idx] = s;
    }
    __syncthreads();

    const float scale = 0.35355339059327376f;   // 1/sqrt(8)
    for (int idx = tid; idx < 8*FF; idx += 256) {
        int h = idx / FF, j = idx - h * FF;
        const float* xr = &xs_s[j*68];
        const float* qr = &qW_s[h*64];
        float s = 0.f;
        #pragma unroll
        for (int k4 = 0; k4 < 16; k4++) {
            float4 a = *(const float4*)(xr + k4*4);
            float4 w = *(const float4*)(qr + k4*4);
            s += a.x*w.x + a.y*w.y + a.z*w.z + a.w*w.w;
        }
        p_s[h*96 + j] = s * scale;
    }
    __syncthreads();

    {
        int w = tid >> 5, lane = tid & 31;
        float m = -3.0e38f;
        for (int j = lane; j < FF; j += 32) m = fmaxf(m, p_s[w*96 + j]);
        #pragma unroll
        for (int o = 16; o > 0; o >>= 1) m = fmaxf(m, __shfl_xor_sync(0xffffffffu, m, o));
        float sum = 0.f;
        for (int j = lane; j < FF; j += 32) {
            float e = __expf(p_s[w*96 + j] - m);
            p_s[w*96 + j] = e; sum += e;
        }
        #pragma unroll
        for (int o = 16; o > 0; o >>= 1) sum += __shfl_xor_sync(0xffffffffu, sum, o);
        float inv = 1.f / sum;
        for (int j = lane; j < FF; j += 32) p_s[w*96 + j] *= inv;
    }
    __syncthreads();

    // a[h][k0..k0+3] = sum_j p[h][j] * xs[j][k0..k0+3]   (128 threads, float4)
    if (tid < 128) {
        const int h = tid >> 4, k4 = (tid & 15) << 2;
        const float* pr = &p_s[h*96];
        float4 acc = make_float4(0.f, 0.f, 0.f, 0.f);
        for (int j = 0; j < FF; j++) {
            float p = pr[j];
            float4 v = *(const float4*)(&xs_s[j*68 + k4]);
            acc.x += p * v.x; acc.y += p * v.y;
            acc.z += p * v.z; acc.w += p * v.w;
        }
        *(float4*)(&a_s[h*64 + k4]) = acc;
    }
    __syncthreads();

    if (tid < 64) {
        int h = tid >> 3;
        float s = 0.f;
        #pragma unroll 8
        for (int k = 0; k < 64; k++) s += a_s[h*64 + k] * __ldg(&Wvs[k*64 + tid]);
        g_y0pre[bt*64 + tid] = s;
    }
}

// ---------------------------------------------------------------------------
// xt = x + y0pre @ WosWt -> tf32 bits (plain layout).
// 512 threads, float2 columns (low reg pressure, higher occupancy).
// ---------------------------------------------------------------------------
__global__ void __launch_bounds__(512) xt_kernel(const float* __restrict__ x) {
    const int r0  = blockIdx.x * 16;
    const int tid = threadIdx.x;     // 512
    __shared__ float y0[16][64];

    for (int idx = tid; idx < 16*64; idx += 512)
        y0[idx >> 6][idx & 63] = g_y0pre[(r0 + (idx >> 6)) * 64 + (idx & 63)];
    __syncthreads();

    const int c = tid * 2;
    float2 acc[16];
    #pragma unroll
    for (int r = 0; r < 16; r++)
        acc[r] = *(const float2*)(x + (size_t)(r0 + r) * DD + c);

    #pragma unroll 4
    for (int k = 0; k < 64; k++) {
        float2 w = *(const float2*)(g_WosWt + k * DD + c);
        #pragma unroll
        for (int r = 0; r < 16; r++) {
            float y = y0[r][k];
            acc[r].x += y * w.x; acc[r].y += y * w.y;
        }
    }
    #pragma unroll
    for (int r = 0; r < 16; r++)
        *(uint2*)(g_xt32 + (size_t)(r0 + r) * DD + c) =
            make_uint2(f2tf32(acc[r].x), f2tf32(acc[r].y));
}

// ---------------------------------------------------------------------------
// tf32 tensor-core GEMM tile (R8-proven): C[128,128] = A[128,1024] @ W[.,128]
// BK=32, register prefetch, fill = LDG.128 + STS.128 only.
// ---------------------------------------------------------------------------
template <bool CVT_OUT>
__device__ __forceinline__ void gemm_tf32_tile(const uint32_t* __restrict__ A32,
                                               const uint32_t* __restrict__ B32,
                                               void* __restrict__ Cv,
                                               int bm, int bn) {
    __shared__ uint32_t As[128][36];   // m-major tf32 bits, pad 36
    __shared__ uint32_t Bs[32][136];   // k-major tf32 bits, pad 136

    const int tid  = threadIdx.x;
    const int warp = tid >> 5, lane = tid & 31;
    const int wm = (warp >> 1) * 32;   // 4 warp-rows
    const int wn = (warp & 1) * 64;    // 2 warp-cols
    const int g = lane >> 2, t = lane & 3;

    const int aRow0 = tid >> 3,  aC = (tid & 7) << 2;
    const int bRow0 = tid >> 5,  bC = (tid & 31) << 2;

    uint4 pa[4], pb[4];
    auto loadA = [&](int k0) {
        #pragma unroll
        for (int i = 0; i < 4; i++)
            pa[i] = *(const uint4*)(A32 + (size_t)(bm + aRow0 + 32*i) * 1024 + k0 + aC);
    };
    auto loadB = [&](int k0) {
        #pragma unroll
        for (int i = 0; i < 4; i++)
            pb[i] = *(const uint4*)(B32 + (size_t)(k0 + bRow0 + 8*i) * 1024 + bn + bC);
    };
    auto storeTiles = [&]() {
        #pragma unroll
        for (int i = 0; i < 4; i++) *(uint4*)&As[aRow0 + 32*i][aC] = pa[i];
        #pragma unroll
        for (int i = 0; i < 4; i++) *(uint4*)&Bs[bRow0 + 8*i][bC] = pb[i];
    };

    float acc[2][8][4];
    #pragma unroll
    for (int mi = 0; mi < 2; mi++)
        #pragma unroll
        for (int ni = 0; ni < 8; ni++)
            #pragma unroll
            for (int r = 0; r < 4; r++) acc[mi][ni][r] = 0.f;

    loadA(0); loadB(0); storeTiles();
    __syncthreads();

    for (int k0 = 0; k0 < 1024; k0 += 32) {
        const bool more = (k0 + 32) < 1024;
        if (more) { loadA(k0 + 32); loadB(k0 + 32); }

        #pragma unroll
        for (int kk = 0; kk < 32; kk += 8) {
            uint32_t a[2][4], b[8][2];
            #pragma unroll
            for (int mi = 0; mi < 2; mi++) {
                int m = wm + mi * 16 + g;
                a[mi][0] = As[m    ][kk + t];
                a[mi][1] = As[m + 8][kk + t];
                a[mi][2] = As[m    ][kk + t + 4];
                a[mi][3] = As[m + 8][kk + t + 4];
            }
            #pragma unroll
            for (int ni = 0; ni < 8; ni++) {
                int n = wn + ni * 8 + g;
                b[ni][0] = Bs[kk + t    ][n];
                b[ni][1] = Bs[kk + t + 4][n];
            }
            #pragma unroll
            for (int mi = 0; mi < 2; mi++)
                #pragma unroll
                for (int ni = 0; ni < 8; ni++)
                    mma_tf32(acc[mi][ni], a[mi], b[ni]);
        }
        __syncthreads();
        if (more) { storeTiles(); __syncthreads(); }
    }

    #pragma unroll
    for (int mi = 0; mi < 2; mi++) {
        int row0 = bm + wm + mi * 16 + g;
        #pragma unroll
        for (int ni = 0; ni < 8; ni++) {
            int col = bn + wn + ni * 8 + t * 2;
            if (CVT_OUT) {
                uint32_t* C = (uint32_t*)Cv;
                *(uint2*)(C + (size_t)row0 * 1024 + col) =
                    make_uint2(f2tf32(acc[mi][ni][0]), f2tf32(acc[mi][ni][1]));
                *(uint2*)(C + (size_t)(row0 + 8) * 1024 + col) =
                    make_uint2(f2tf32(acc[mi][ni][2]), f2tf32(acc[mi][ni][3]));
            } else {
                float* C = (float*)Cv;
                *(float2*)(C + (size_t)row0 * 1024 + col) =
                    make_float2(acc[mi][ni][0], acc[mi][ni][1]);
                *(float2*)(C + (size_t)(row0 + 8) * 1024 + col) =
                    make_float2(acc[mi][ni][2], acc[mi][ni][3]);
            }
        }
    }
}

__global__ void __launch_bounds__(256, 2) qkv_gemm_kernel() {
    int which = blockIdx.x >> 3;                // 0..2
    int bn    = (blockIdx.x & 7) * 128;
    int bm    = blockIdx.y * 128;
    const uint32_t* W = g_w32 + (size_t)which * DD * DD;
    uint32_t* C = g_qkv32 + (size_t)which * MM * DD;
    gemm_tf32_tile<true>(g_xt32, W, C, bm, bn);
}

__global__ void __launch_bounds__(256, 2) out_gemm_kernel(float* __restrict__ C) {
    gemm_tf32_tile<false>(g_attnout32, g_w32 + 3 * (size_t)DD * DD, C,
                          blockIdx.y * 128, blockIdx.x * 128);
}

// ---------------------------------------------------------------------------
// Temporal attention: block-diagonal flash on tf32 tensor cores.
// ---------------------------------------------------------------------------
__global__ void __launch_bounds__(256) temporal_attn_kernel(const int* __restrict__ valid_len) {
    __shared__ uint32_t Qs [32][132];
    __shared__ uint32_t KVs[32][132];
    __shared__ float    Ss [32][36];
    __shared__ float m_s[32], l_s[32], al_s[32];
    __shared__ int   lo_s[32], hi_s[32];

    const int qt = blockIdx.x, h = blockIdx.y, b = blockIdx.z;
    const int tid = threadIdx.x;
    const int warp = tid >> 5, lane = tid & 31;
    const int g = lane >> 2, t = lane & 3;
    const int q0 = qt * 32;
    const uint32_t* Q = g_qkv32;
    const uint32_t* K = g_qkv32 + (size_t)MM * DD;
    const uint32_t* V = g_qkv32 + 2 * (size_t)MM * DD;
    const int l = valid_len[b];

    if (tid < 32) {
        int i = q0 + tid;
        int lo, hi;
        const int dv = (h >> 1) + 1;
        if (i < l) {
            int c = (i * dv) / l;
            lo = (c * l + dv - 1) / dv;
            hi = ((c + 1) * l - 1) / dv + 1;
            if (hi > l) hi = l;
        } else { lo = l; hi = TT; }
        lo_s[tid] = lo; hi_s[tid] = hi;
        m_s[tid] = -1e30f; l_s[tid] = 0.f;
    }
    for (int f = tid; f < 32*32; f += 256) {
        int r = f >> 5, c4 = (f & 31) << 2;
        *(uint4*)&Qs[r][c4] =
            *(const uint4*)(Q + (size_t)(b*TT + q0 + r)*DD + h*128 + c4);
    }
    __syncthreads();
    const int bLo = lo_s[0], bHi = hi_s[31];   // lo/hi monotone in i

    const int wmS = (warp >> 2) * 16, wnS = (warp & 3) * 8;   // S: 16x8 per warp
    const int wmP = (warp >> 2) * 16, wnP = (warp & 3) * 32;  // PV: 16x32 per warp
    const float scale = 0.08838834764831845f;  // 1/sqrt(128)

    float O[4][4];
    #pragma unroll
    for (int ni = 0; ni < 4; ni++)
        #pragma unroll
        for (int r = 0; r < 4; r++) O[ni][r] = 0.f;

    for (int kt = bLo & ~31; kt < bHi; kt += 32) {
        for (int f = tid; f < 32*32; f += 256) {
            int r = f >> 5, c4 = (f & 31) << 2;
            int j = kt + r; if (j > TT - 1) j = TT - 1;
            *(uint4*)&KVs[r][c4] =
                *(const uint4*)(K + (size_t)(b*TT + j)*DD + h*128 + c4);
        }
        __syncthreads();

        float sc[4] = {0.f, 0.f, 0.f, 0.f};
        #pragma unroll
        for (int kk = 0; kk < 128; kk += 8) {
            uint32_t a[4], bb[2];
            a[0] = Qs[wmS + g    ][kk + t];
            a[1] = Qs[wmS + g + 8][kk + t];
            a[2] = Qs[wmS + g    ][kk + t + 4];
            a[3] = Qs[wmS + g + 8][kk + t + 4];
            bb[0] = KVs[wnS + g][kk + t];
            bb[1] = KVs[wnS + g][kk + t + 4];
            mma_tf32(sc, a, bb);
        }
        Ss[wmS + g    ][wnS + 2*t    ] = sc[0] * scale;
        Ss[wmS + g    ][wnS + 2*t + 1] = sc[1] * scale;
        Ss[wmS + g + 8][wnS + 2*t    ] = sc[2] * scale;
        Ss[wmS + g + 8][wnS + 2*t + 1] = sc[3] * scale;
        __syncthreads();

        if (tid < 32) {
            const int lo = lo_s[tid], hi = hi_s[tid];
            float mo = m_s[tid];
            float rmax = -3e38f;
            #pragma unroll 8
            for (int j = 0; j < 32; j++) {
                int jg = kt + j;
                float s = (jg >= lo && jg < hi) ? Ss[tid][j] : -3e38f;
                Ss[tid][j] = s;
                rmax = fmaxf(rmax, s);
            }
            float mn = fmaxf(mo, rmax);
            float alpha = __expf(mo - mn);
            float rs = 0.f;
            #pragma unroll 8
            for (int j = 0; j < 32; j++) {
                float p = __expf(Ss[tid][j] - mn);
                Ss[tid][j] = p;
                rs += p;
            }
            l_s[tid] = l_s[tid] * alpha + rs;
            m_s[tid] = mn;
            al_s[tid] = alpha;
        }
        for (int f = tid; f < 32*32; f += 256) {
            int r = f >> 5, c4 = (f & 31) << 2;
            int j = kt + r; if (j > TT - 1) j = TT - 1;
            *(uint4*)&KVs[r][c4] =
                *(const uint4*)(V + (size_t)(b*TT + j)*DD + h*128 + c4);
        }
        __syncthreads();

        {
            float a0 = al_s[wmP + g], a1 = al_s[wmP + g + 8];
            #pragma unroll
            for (int ni = 0; ni < 4; ni++) {
                O[ni][0] *= a0; O[ni][1] *= a0;
                O[ni][2] *= a1; O[ni][3] *= a1;
            }
        }
        #pragma unroll
        for (int kk = 0; kk < 32; kk += 8) {
            uint32_t a[4];
            a[0] = f2tf32(Ss[wmP + g    ][kk + t]);
            a[1] = f2tf32(Ss[wmP + g + 8][kk + t]);
            a[2] = f2tf32(Ss[wmP + g    ][kk + t + 4]);
            a[3] = f2tf32(Ss[wmP + g + 8][kk + t + 4]);
            #pragma unroll
            for (int ni = 0; ni < 4; ni++) {
                uint32_t bb[2];
                int n = wnP + ni * 8 + g;
                bb[0] = KVs[kk + t    ][n];
                bb[1] = KVs[kk + t + 4][n];
                mma_tf32(O[ni], a, bb);
            }
        }
        __syncthreads();
    }

    {
        float inv0 = 1.f / l_s[wmP + g];
        float inv1 = 1.f / l_s[wmP + g + 8];
        const size_t r0 = (size_t)(b*TT + q0 + wmP + g) * DD;
        const size_t r1 = (size_t)(b*TT + q0 + wmP + g + 8) * DD;
        #pragma unroll
        for (int ni = 0; ni < 4; ni++) {
            int col = h*128 + wnP + ni*8 + 2*t;
            *(uint2*)(g_attnout32 + r0 + col) =
                make_uint2(f2tf32(O[ni][0]*inv0), f2tf32(O[ni][1]*inv0));
            *(uint2*)(g_attnout32 + r1 + col) =
                make_uint2(f2tf32(O[ni][2]*inv1), f2tf32(O[ni][3]*inv1));
        }
    }
}

// ---------------------------------------------------------------------------
extern "C" void kernel_launch(void* const* d_in, const int* in_sizes, int n_in,
                              void* d_out, int out_size) {
    const float* x   = (const float*)d_in[0];
    const float* xs  = (const float*)d_in[1];
    const int*   vl  = (const int*)  d_in[2];
    const float* Wq  = (const float*)d_in[3];
    const float* Wk  = (const float*)d_in[4];
    const float* Wv  = (const float*)d_in[5];
    const float* Wo  = (const float*)d_in[6];
    const float* Wqs = (const float*)d_in[7];
    const float* Wks = (const float*)d_in[8];
    const float* Wvs = (const float*)d_in[9];
    const float* Wos = (const float*)d_in[10];
    const float* Wt  = (const float*)d_in[11];
    float* out = (float*)d_out;

    prep_w_kernel<<<dim3(1024, 4), 256>>>(Wq, Wk, Wv, Wo);
    woswt_kernel<<<256, 256>>>(Wos, Wt);
    spectral_kernel<<<MM, 256>>>(xs, Wqs, Wks, Wvs);
    xt_kernel<<<MM/16, 512>>>(x);
    qkv_gemm_kernel<<<dim3(24, 16), 256>>>();
    temporal_attn_kernel<<<dim3(TT/32, HH, BB), 256>>>(vl);
    out_gemm_kernel<<<dim3(8, 16), 256>>>(out);
}

// round 13
// speedup vs baseline: 1.1179x; 1.0358x over previous
#include <cuda_runtime.h>
#include <cstdint>

// Shapes (fixed by the problem)
#define BB   4
#define TT   512
#define FF   93
#define DSS  64
#define DD   1024
#define HH   8
#define MM   (BB*TT)      // 2048 rows

// Scratch (static device allocations; no cudaMalloc allowed)
__device__ float    g_y0pre[MM*DSS];      // spectral fct output pre-Wos  [2048,64]
__device__ float    g_WosWt[DSS*DD];      // Wos @ Wt                     [64,1024]
__device__ uint32_t g_xt32[MM*DD];        // temporal input, tf32 bits (plain [m][k])
__device__ uint32_t g_w32[4*DD*DD];       // Wq,Wk,Wv,Wo tf32 bits (plain [k][n])
__device__ uint32_t g_qkv32[3*MM*DD];     // Q,K,V as tf32 bit patterns
__device__ uint32_t g_attnout32[MM*DD];   // attention out, tf32 bits (plain [m][k])

// GEMM dynamic smem: 2 stages of (As[128][36] + Bs[32][136]) uint32
#define GEMM_AS_STRIDE (128*36)
#define GEMM_BS_STRIDE (32*136)
#define GEMM_SMEM_BYTES ((2*(GEMM_AS_STRIDE + GEMM_BS_STRIDE)) * 4)

// ---------------------------------------------------------------------------
// helpers: tf32 convert + mma + cp.async
// ---------------------------------------------------------------------------
__device__ __forceinline__ uint32_t f2tf32(float x) {
    uint32_t r;
    asm("cvt.rna.tf32.f32 %0, %1;" : "=r"(r) : "f"(x));
    return r;
}
__device__ __forceinline__ void mma_tf32(float c[4], const uint32_t a[4], const uint32_t b[2]) {
    asm volatile(
        "mma.sync.aligned.m16n8k8.row.col.f32.tf32.tf32.f32 "
        "{%0,%1,%2,%3}, {%4,%5,%6,%7}, {%8,%9}, {%0,%1,%2,%3};"
        : "+f"(c[0]), "+f"(c[1]), "+f"(c[2]), "+f"(c[3])
        : "r"(a[0]), "r"(a[1]), "r"(a[2]), "r"(a[3]), "r"(b[0]), "r"(b[1]));
}
__device__ __forceinline__ void cp16(void* dst_smem, const void* src) {
    uint32_t d = (uint32_t)__cvta_generic_to_shared(dst_smem);
    asm volatile("cp.async.cg.shared.global [%0], [%1], 16;" :: "r"(d), "l"(src));
}
__device__ __forceinline__ void cp_commit() {
    asm volatile("cp.async.commit_group;");
}
__device__ __forceinline__ void cp_wait_all() {
    asm volatile("cp.async.wait_group 0;");
}

// ---------------------------------------------------------------------------
// prep: convert weights to tf32 bits (split so spectral lands at launch #3)
// ---------------------------------------------------------------------------
__global__ void prep_qkvw_kernel(const float* __restrict__ Wq,
                                 const float* __restrict__ Wk,
                                 const float* __restrict__ Wv) {
    const int z = blockIdx.y;
    const float* S = (z == 0) ? Wq : (z == 1) ? Wk : Wv;
    int i = (blockIdx.x * 256 + threadIdx.x) * 4;
    float4 v = *(const float4*)(S + i);
    *(uint4*)(g_w32 + (size_t)z * DD * DD + i) =
        make_uint4(f2tf32(v.x), f2tf32(v.y), f2tf32(v.z), f2tf32(v.w));
}
__global__ void prep_wo_kernel(const float* __restrict__ Wo) {
    int i = (blockIdx.x * 256 + threadIdx.x) * 4;
    float4 v = *(const float4*)(Wo + i);
    *(uint4*)(g_w32 + 3 * (size_t)DD * DD + i) =
        make_uint4(f2tf32(v.x), f2tf32(v.y), f2tf32(v.z), f2tf32(v.w));
}

// ---------------------------------------------------------------------------
// WosWt = Wos[64,64] @ Wt[64,1024]
// ---------------------------------------------------------------------------
__global__ void woswt_kernel(const float* __restrict__ Wos, const float* __restrict__ Wt) {
    int idx = blockIdx.x * 256 + threadIdx.x;   // 65536 outputs
    int r = idx >> 10, c = idx & 1023;
    float s = 0.f;
    #pragma unroll 8
    for (int k = 0; k < 64; k++) s += Wos[r*64 + k] * Wt[k*1024 + c];
    g_WosWt[idx] = s;
}

// ---------------------------------------------------------------------------
// Spectral attention, fct query only (row-0 mask is all-True).
// ---------------------------------------------------------------------------
__global__ void spectral_kernel(const float* __restrict__ xs,
                                const float* __restrict__ Wqs,
                                const float* __restrict__ Wks,
                                const float* __restrict__ Wvs) {
    __shared__ float xs_s[FF*68];
    __shared__ float q0_s[64];
    __shared__ float qW_s[8*64];
    __shared__ float p_s[8*96];
    __shared__ float a_s[8*64];

    const int bt  = blockIdx.x;
    const int tid = threadIdx.x;   // 256
    const float* xp = xs + (size_t)bt * FF * DSS;

    for (int idx = tid; idx < FF*DSS; idx += 256)
        xs_s[(idx >> 6) * 68 + (idx & 63)] = xp[idx];
    __syncthreads();

    if (tid < 64) {
        float s = 0.f;
        #pragma unroll 8
        for (int k = 0; k < 64; k++) s += xs_s[k] * __ldg(&Wqs[k*64 + tid]);
        q0_s[tid] = s;
    }
    __syncthreads();

    // qW[h][k] = sum_d q0[h*8+d] * Wks[k][h*8+d]
    for (int idx = tid; idx < 512; idx += 256) {
        int h = idx >> 6, k = idx & 63;
        float s = 0.f;
        #pragma unroll
        for (int d = 0; d < 8; d++) s += q0_s[h*8 + d] * __ldg(&Wks[k*64 + h*8 + d]);
        qW_s[idx] = s;
    }
    __syncthreads();

    const float scale = 0.35355339059327376f;   // 1/sqrt(8)
    for (int idx = tid; idx < 8*FF; idx += 256) {
        int h = idx / FF, j = idx - h * FF;
        const float* xr = &xs_s[j*68];
        const float* qr = &qW_s[h*64];
        float s = 0.f;
        #pragma unroll
        for (int k4 = 0; k4 < 16; k4++) {
            float4 a = *(const float4*)(xr + k4*4);
            float4 w = *(const float4*)(qr + k4*4);
            s += a.x*w.x + a.y*w.y + a.z*w.z + a.w*w.w;
        }
        p_s[h*96 + j] = s * scale;
    }
    __syncthreads();

    {
        int w = tid >> 5, lane = tid & 31;
        float m = -3.0e38f;
        for (int j = lane; j < FF; j += 32) m = fmaxf(m, p_s[w*96 + j]);
        #pragma unroll
        for (int o = 16; o > 0; o >>= 1) m = fmaxf(m, __shfl_xor_sync(0xffffffffu, m, o));
        float sum = 0.f;
        for (int j = lane; j < FF; j += 32) {
            float e = __expf(p_s[w*96 + j] - m);
            p_s[w*96 + j] = e; sum += e;
        }
        #pragma unroll
        for (int o = 16; o > 0; o >>= 1) sum += __shfl_xor_sync(0xffffffffu, sum, o);
        float inv = 1.f / sum;
        for (int j = lane; j < FF; j += 32) p_s[w*96 + j] *= inv;
    }
    __syncthreads();

    // a[h][k0..k0+3] = sum_j p[h][j] * xs[j][k0..k0+3]   (128 threads, float4)
    if (tid < 128) {
        const int h = tid >> 4, k4 = (tid & 15) << 2;
        const float* pr = &p_s[h*96];
        float4 acc = make_float4(0.f, 0.f, 0.f, 0.f);
        for (int j = 0; j < FF; j++) {
            float p = pr[j];
            float4 v = *(const float4*)(&xs_s[j*68 + k4]);
            acc.x += p * v.x; acc.y += p * v.y;
            acc.z += p * v.z; acc.w += p * v.w;
        }
        *(float4*)(&a_s[h*64 + k4]) = acc;
    }
    __syncthreads();

    if (tid < 64) {
        int h = tid >> 3;
        float s = 0.f;
        #pragma unroll 8
        for (int k = 0; k < 64; k++) s += a_s[h*64 + k] * __ldg(&Wvs[k*64 + tid]);
        g_y0pre[bt*64 + tid] = s;
    }
}

// ---------------------------------------------------------------------------
// xt = x + y0pre @ WosWt -> tf32 bits (plain layout).
// ---------------------------------------------------------------------------
__global__ void __launch_bounds__(512) xt_kernel(const float* __restrict__ x) {
    const int r0  = blockIdx.x * 16;
    const int tid = threadIdx.x;     // 512
    __shared__ float y0[16][64];

    for (int idx = tid; idx < 16*64; idx += 512)
        y0[idx >> 6][idx & 63] = g_y0pre[(r0 + (idx >> 6)) * 64 + (idx & 63)];
    __syncthreads();

    const int c = tid * 2;
    float2 acc[16];
    #pragma unroll
    for (int r = 0; r < 16; r++)
        acc[r] = *(const float2*)(x + (size_t)(r0 + r) * DD + c);

    #pragma unroll 4
    for (int k = 0; k < 64; k++) {
        float2 w = *(const float2*)(g_WosWt + k * DD + c);
        #pragma unroll
        for (int r = 0; r < 16; r++) {
            float y = y0[r][k];
            acc[r].x += y * w.x; acc[r].y += y * w.y;
        }
    }
    #pragma unroll
    for (int r = 0; r < 16; r++)
        *(uint2*)(g_xt32 + (size_t)(r0 + r) * DD + c) =
            make_uint2(f2tf32(acc[r].x), f2tf32(acc[r].y));
}

// ---------------------------------------------------------------------------
// tf32 tensor-core GEMM, cp.async DOUBLE-BUFFERED, BK=32, ONE sync per tile.
// Dynamic smem: 2 stages of As[128][36] + Bs[32][136] (70 KB).
// Ordering proof: iter-k mma (reads stage k&1) happens before iter-k+1's
// __syncthreads, which happens before iter-k+1's issue into stage k&1.
// ---------------------------------------------------------------------------
template <bool CVT_OUT>
__device__ __forceinline__ void gemm_cp_tile(const uint32_t* __restrict__ A32,
                                             const uint32_t* __restrict__ B32,
                                             void* __restrict__ Cv,
                                             int bm, int bn) {
    extern __shared__ uint32_t smdyn[];
    uint32_t* AsBase = smdyn;                        // [2][128][36]
    uint32_t* BsBase = smdyn + 2 * GEMM_AS_STRIDE;   // [2][32][136]

    const int tid  = threadIdx.x;
    const int warp = tid >> 5, lane = tid & 31;
    const int wm = (warp >> 1) * 32;   // 4 warp-rows
    const int wn = (warp & 1) * 64;    // 2 warp-cols
    const int g = lane >> 2, t = lane & 3;

    const int aRow0 = tid >> 3,  aC = (tid & 7) << 2;   // +32 rows per i (4 iters)
    const int bRow0 = tid >> 5,  bC = (tid & 31) << 2;  // +8 rows per i (4 iters)

    auto issue = [&](int k0, int s) {
        uint32_t* As = AsBase + s * GEMM_AS_STRIDE;
        uint32_t* Bs = BsBase + s * GEMM_BS_STRIDE;
        #pragma unroll
        for (int i = 0; i < 4; i++)
            cp16(&As[(aRow0 + 32*i) * 36 + aC],
                 A32 + (size_t)(bm + aRow0 + 32*i) * 1024 + k0 + aC);
        #pragma unroll
        for (int i = 0; i < 4; i++)
            cp16(&Bs[(bRow0 + 8*i) * 136 + bC],
                 B32 + (size_t)(k0 + bRow0 + 8*i) * 1024 + bn + bC);
        cp_commit();
    };

    float acc[2][8][4];
    #pragma unroll
    for (int mi = 0; mi < 2; mi++)
        #pragma unroll
        for (int ni = 0; ni < 8; ni++)
            #pragma unroll
            for (int r = 0; r < 4; r++) acc[mi][ni][r] = 0.f;

    issue(0, 0);

    for (int kt = 0; kt < 32; kt++) {
        const int s = kt & 1;
        cp_wait_all();          // stage s arrived (issued last iter, overlapped mma)
        __syncthreads();        // all warps see stage s; all done reading stage s^1
        if (kt + 1 < 32) issue((kt + 1) * 32, s ^ 1);

        const uint32_t* As = AsBase + s * GEMM_AS_STRIDE;
        const uint32_t* Bs = BsBase + s * GEMM_BS_STRIDE;
        #pragma unroll
        for (int kk = 0; kk < 32; kk += 8) {
            uint32_t a[2][4], b[8][2];
            #pragma unroll
            for (int mi = 0; mi < 2; mi++) {
                int m = wm + mi * 16 + g;
                a[mi][0] = As[m * 36 + kk + t];
                a[mi][1] = As[(m + 8) * 36 + kk + t];
                a[mi][2] = As[m * 36 + kk + t + 4];
                a[mi][3] = As[(m + 8) * 36 + kk + t + 4];
            }
            #pragma unroll
            for (int ni = 0; ni < 8; ni++) {
                int n = wn + ni * 8 + g;
                b[ni][0] = Bs[(kk + t) * 136 + n];
                b[ni][1] = Bs[(kk + t + 4) * 136 + n];
            }
            #pragma unroll
            for (int mi = 0; mi < 2; mi++)
                #pragma unroll
                for (int ni = 0; ni < 8; ni++)
                    mma_tf32(acc[mi][ni], a[mi], b[ni]);
        }
    }

    #pragma unroll
    for (int mi = 0; mi < 2; mi++) {
        int row0 = bm + wm + mi * 16 + g;
        #pragma unroll
        for (int ni = 0; ni < 8; ni++) {
            int col = bn + wn + ni * 8 + t * 2;
            if (CVT_OUT) {
                uint32_t* C = (uint32_t*)Cv;
                *(uint2*)(C + (size_t)row0 * 1024 + col) =
                    make_uint2(f2tf32(acc[mi][ni][0]), f2tf32(acc[mi][ni][1]));
                *(uint2*)(C + (size_t)(row0 + 8) * 1024 + col) =
                    make_uint2(f2tf32(acc[mi][ni][2]), f2tf32(acc[mi][ni][3]));
            } else {
                float* C = (float*)Cv;
                *(float2*)(C + (size_t)row0 * 1024 + col) =
                    make_float2(acc[mi][ni][0], acc[mi][ni][1]);
                *(float2*)(C + (size_t)(row0 + 8) * 1024 + col) =
                    make_float2(acc[mi][ni][2], acc[mi][ni][3]);
            }
        }
    }
}

__global__ void __launch_bounds__(256, 2) qkv_gemm_kernel() {
    int which = blockIdx.x >> 3;                // 0..2
    int bn    = (blockIdx.x & 7) * 128;
    int bm    = blockIdx.y * 128;
    const uint32_t* W = g_w32 + (size_t)which * DD * DD;
    uint32_t* C = g_qkv32 + (size_t)which * MM * DD;
    gemm_cp_tile<true>(g_xt32, W, C, bm, bn);
}

__global__ void __launch_bounds__(256, 2) out_gemm_kernel(float* __restrict__ C) {
    gemm_cp_tile<false>(g_attnout32, g_w32 + 3 * (size_t)DD * DD, C,
                        blockIdx.y * 128, blockIdx.x * 128);
}

// ---------------------------------------------------------------------------
// Temporal attention: block-diagonal flash on tf32 tensor cores.
// ---------------------------------------------------------------------------
__global__ void __launch_bounds__(256) temporal_attn_kernel(const int* __restrict__ valid_len) {
    __shared__ uint32_t Qs [32][132];
    __shared__ uint32_t KVs[32][132];
    __shared__ float    Ss [32][36];
    __shared__ float m_s[32], l_s[32], al_s[32];
    __shared__ int   lo_s[32], hi_s[32];

    const int qt = blockIdx.x, h = blockIdx.y, b = blockIdx.z;
    const int tid = threadIdx.x;
    const int warp = tid >> 5, lane = tid & 31;
    const int g = lane >> 2, t = lane & 3;
    const int q0 = qt * 32;
    const uint32_t* Q = g_qkv32;
    const uint32_t* K = g_qkv32 + (size_t)MM * DD;
    const uint32_t* V = g_qkv32 + 2 * (size_t)MM * DD;
    const int l = valid_len[b];

    if (tid < 32) {
        int i = q0 + tid;
        int lo, hi;
        const int dv = (h >> 1) + 1;
        if (i < l) {
            int c = (i * dv) / l;
            lo = (c * l + dv - 1) / dv;
            hi = ((c + 1) * l - 1) / dv + 1;
            if (hi > l) hi = l;
        } else { lo = l; hi = TT; }
        lo_s[tid] = lo; hi_s[tid] = hi;
        m_s[tid] = -1e30f; l_s[tid] = 0.f;
    }
    for (int f = tid; f < 32*32; f += 256) {
        int r = f >> 5, c4 = (f & 31) << 2;
        *(uint4*)&Qs[r][c4] =
            *(const uint4*)(Q + (size_t)(b*TT + q0 + r)*DD + h*128 + c4);
    }
    __syncthreads();
    const int bLo = lo_s[0], bHi = hi_s[31];   // lo/hi monotone in i

    const int wmS = (warp >> 2) * 16, wnS = (warp & 3) * 8;   // S: 16x8 per warp
    const int wmP = (warp >> 2) * 16, wnP = (warp & 3) * 32;  // PV: 16x32 per warp
    const float scale = 0.08838834764831845f;  // 1/sqrt(128)

    float O[4][4];
    #pragma unroll
    for (int ni = 0; ni < 4; ni++)
        #pragma unroll
        for (int r = 0; r < 4; r++) O[ni][r] = 0.f;

    for (int kt = bLo & ~31; kt < bHi; kt += 32) {
        for (int f = tid; f < 32*32; f += 256) {
            int r = f >> 5, c4 = (f & 31) << 2;
            int j = kt + r; if (j > TT - 1) j = TT - 1;
            *(uint4*)&KVs[r][c4] =
                *(const uint4*)(K + (size_t)(b*TT + j)*DD + h*128 + c4);
        }
        __syncthreads();

        float sc[4] = {0.f, 0.f, 0.f, 0.f};
        #pragma unroll
        for (int kk = 0; kk < 128; kk += 8) {
            uint32_t a[4], bb[2];
            a[0] = Qs[wmS + g    ][kk + t];
            a[1] = Qs[wmS + g + 8][kk + t];
            a[2] = Qs[wmS + g    ][kk + t + 4];
            a[3] = Qs[wmS + g + 8][kk + t + 4];
            bb[0] = KVs[wnS + g][kk + t];
            bb[1] = KVs[wnS + g][kk + t + 4];
            mma_tf32(sc, a, bb);
        }
        Ss[wmS + g    ][wnS + 2*t    ] = sc[0] * scale;
        Ss[wmS + g    ][wnS + 2*t + 1] = sc[1] * scale;
        Ss[wmS + g + 8][wnS + 2*t    ] = sc[2] * scale;
        Ss[wmS + g + 8][wnS + 2*t + 1] = sc[3] * scale;
        __syncthreads();

        if (tid < 32) {
            const int lo = lo_s[tid], hi = hi_s[tid];
            float mo = m_s[tid];
            float rmax = -3e38f;
            #pragma unroll 8
            for (int j = 0; j < 32; j++) {
                int jg = kt + j;
                float s = (jg >= lo && jg < hi) ? Ss[tid][j] : -3e38f;
                Ss[tid][j] = s;
                rmax = fmaxf(rmax, s);
            }
            float mn = fmaxf(mo, rmax);
            float alpha = __expf(mo - mn);
            float rs = 0.f;
            #pragma unroll 8
            for (int j = 0; j < 32; j++) {
                float p = __expf(Ss[tid][j] - mn);
                Ss[tid][j] = p;
                rs += p;
            }
            l_s[tid] = l_s[tid] * alpha + rs;
            m_s[tid] = mn;
            al_s[tid] = alpha;
        }
        for (int f = tid; f < 32*32; f += 256) {
            int r = f >> 5, c4 = (f & 31) << 2;
            int j = kt + r; if (j > TT - 1) j = TT - 1;
            *(uint4*)&KVs[r][c4] =
                *(const uint4*)(V + (size_t)(b*TT + j)*DD + h*128 + c4);
        }
        __syncthreads();

        {
            float a0 = al_s[wmP + g], a1 = al_s[wmP + g + 8];
            #pragma unroll
            for (int ni = 0; ni < 4; ni++) {
                O[ni][0] *= a0; O[ni][1] *= a0;
                O[ni][2] *= a1; O[ni][3] *= a1;
            }
        }
        #pragma unroll
        for (int kk = 0; kk < 32; kk += 8) {
            uint32_t a[4];
            a[0] = f2tf32(Ss[wmP + g    ][kk + t]);
            a[1] = f2tf32(Ss[wmP + g + 8][kk + t]);
            a[2] = f2tf32(Ss[wmP + g    ][kk + t + 4]);
            a[3] = f2tf32(Ss[wmP + g + 8][kk + t + 4]);
            #pragma unroll
            for (int ni = 0; ni < 4; ni++) {
                uint32_t bb[2];
                int n = wnP + ni * 8 + g;
                bb[0] = KVs[kk + t    ][n];
                bb[1] = KVs[kk + t + 4][n];
                mma_tf32(O[ni], a, bb);
            }
        }
        __syncthreads();
    }

    {
        float inv0 = 1.f / l_s[wmP + g];
        float inv1 = 1.f / l_s[wmP + g + 8];
        const size_t r0 = (size_t)(b*TT + q0 + wmP + g) * DD;
        const size_t r1 = (size_t)(b*TT + q0 + wmP + g + 8) * DD;
        #pragma unroll
        for (int ni = 0; ni < 4; ni++) {
            int col = h*128 + wnP + ni*8 + 2*t;
            *(uint2*)(g_attnout32 + r0 + col) =
                make_uint2(f2tf32(O[ni][0]*inv0), f2tf32(O[ni][1]*inv0));
            *(uint2*)(g_attnout32 + r1 + col) =
                make_uint2(f2tf32(O[ni][2]*inv1), f2tf32(O[ni][3]*inv1));
        }
    }
}

// ---------------------------------------------------------------------------
extern "C" void kernel_launch(void* const* d_in, const int* in_sizes, int n_in,
                              void* d_out, int out_size) {
    const float* x   = (const float*)d_in[0];
    const float* xs  = (const float*)d_in[1];
    const int*   vl  = (const int*)  d_in[2];
    const float* Wq  = (const float*)d_in[3];
    const float* Wk  = (const float*)d_in[4];
    const float* Wv  = (const float*)d_in[5];
    const float* Wo  = (const float*)d_in[6];
    const float* Wqs = (const float*)d_in[7];
    const float* Wks = (const float*)d_in[8];
    const float* Wvs = (const float*)d_in[9];
    const float* Wos = (const float*)d_in[10];
    const float* Wt  = (const float*)d_in[11];
    float* out = (float*)d_out;

    cudaFuncSetAttribute(qkv_gemm_kernel,
                         cudaFuncAttributeMaxDynamicSharedMemorySize, GEMM_SMEM_BYTES);
    cudaFuncSetAttribute(out_gemm_kernel,
                         cudaFuncAttributeMaxDynamicSharedMemorySize, GEMM_SMEM_BYTES);

    woswt_kernel<<<256, 256>>>(Wos, Wt);                       // 0
    prep_qkvw_kernel<<<dim3(1024, 3), 256>>>(Wq, Wk, Wv);      // 1
    prep_wo_kernel<<<1024, 256>>>(Wo);                         // 2
    spectral_kernel<<<MM, 256>>>(xs, Wqs, Wks, Wvs);           // 3  <- ncu capture slot
    xt_kernel<<<MM/16, 512>>>(x);                              // 4
    qkv_gemm_kernel<<<dim3(24, 16), 256, GEMM_SMEM_BYTES>>>(); // 5
    temporal_attn_kernel<<<dim3(TT/32, HH, BB), 256>>>(vl);    // 6
    out_gemm_kernel<<<dim3(8, 16), 256, GEMM_SMEM_BYTES>>>(out); // 7
}

// round 14
// speedup vs baseline: 1.1387x; 1.0186x over previous
#include <cuda_runtime.h>
#include <cstdint>

// Shapes (fixed by the problem)
#define BB   4
#define TT   512
#define FF   93
#define DSS  64
#define DD   1024
#define HH   8
#define MM   (BB*TT)      // 2048 rows

// Scratch (static device allocations; no cudaMalloc allowed)
__device__ float    g_y0pre[MM*DSS];      // spectral fct output pre-Wos  [2048,64]
__device__ float    g_WosWt[DSS*DD];      // Wos @ Wt                     [64,1024]
__device__ uint32_t g_xt32[MM*DD];        // temporal input, tf32 bits (plain [m][k])
__device__ uint32_t g_w32[4*DD*DD];       // Wq,Wk,Wv,Wo tf32 bits (plain [k][n])
__device__ uint32_t g_qkv32[3*MM*DD];     // Q,K,V as tf32 bit patterns
__device__ uint32_t g_attnout32[MM*DD];   // attention out, tf32 bits (plain [m][k])

// GEMM dynamic smem: 2 stages of (As[128][36] + Bs[32][136]) uint32
#define GEMM_AS_STRIDE (128*36)
#define GEMM_BS_STRIDE (32*136)
#define GEMM_SMEM_BYTES ((2*(GEMM_AS_STRIDE + GEMM_BS_STRIDE)) * 4)

// ---------------------------------------------------------------------------
// helpers: tf32 convert + mma + cp.async
// ---------------------------------------------------------------------------
__device__ __forceinline__ uint32_t f2tf32(float x) {
    uint32_t r;
    asm("cvt.rna.tf32.f32 %0, %1;" : "=r"(r) : "f"(x));
    return r;
}
__device__ __forceinline__ void mma_tf32(float c[4], const uint32_t a[4], const uint32_t b[2]) {
    asm volatile(
        "mma.sync.aligned.m16n8k8.row.col.f32.tf32.tf32.f32 "
        "{%0,%1,%2,%3}, {%4,%5,%6,%7}, {%8,%9}, {%0,%1,%2,%3};"
        : "+f"(c[0]), "+f"(c[1]), "+f"(c[2]), "+f"(c[3])
        : "r"(a[0]), "r"(a[1]), "r"(a[2]), "r"(a[3]), "r"(b[0]), "r"(b[1]));
}
__device__ __forceinline__ void cp16(void* dst_smem, const void* src) {
    uint32_t d = (uint32_t)__cvta_generic_to_shared(dst_smem);
    asm volatile("cp.async.cg.shared.global [%0], [%1], 16;" :: "r"(d), "l"(src));
}
__device__ __forceinline__ void cp_commit() {
    asm volatile("cp.async.commit_group;");
}
__device__ __forceinline__ void cp_wait_all() {
    asm volatile("cp.async.wait_group 0;");
}

// ---------------------------------------------------------------------------
// prep: convert weights to tf32 bits (split so spectral lands at launch #3)
// ---------------------------------------------------------------------------
__global__ void prep_qkvw_kernel(const float* __restrict__ Wq,
                                 const float* __restrict__ Wk,
                                 const float* __restrict__ Wv) {
    const int z = blockIdx.y;
    const float* S = (z == 0) ? Wq : (z == 1) ? Wk : Wv;
    int i = (blockIdx.x * 256 + threadIdx.x) * 4;
    float4 v = *(const float4*)(S + i);
    *(uint4*)(g_w32 + (size_t)z * DD * DD + i) =
        make_uint4(f2tf32(v.x), f2tf32(v.y), f2tf32(v.z), f2tf32(v.w));
}
__global__ void prep_wo_kernel(const float* __restrict__ Wo) {
    int i = (blockIdx.x * 256 + threadIdx.x) * 4;
    float4 v = *(const float4*)(Wo + i);
    *(uint4*)(g_w32 + 3 * (size_t)DD * DD + i) =
        make_uint4(f2tf32(v.x), f2tf32(v.y), f2tf32(v.z), f2tf32(v.w));
}

// ---------------------------------------------------------------------------
// WosWt = Wos[64,64] @ Wt[64,1024]
// ---------------------------------------------------------------------------
__global__ void woswt_kernel(const float* __restrict__ Wos, const float* __restrict__ Wt) {
    int idx = blockIdx.x * 256 + threadIdx.x;   // 65536 outputs
    int r = idx >> 10, c = idx & 1023;
    float s = 0.f;
    #pragma unroll 8
    for (int k = 0; k < 64; k++) s += Wos[r*64 + k] * Wt[k*1024 + c];
    g_WosWt[idx] = s;
}

// ---------------------------------------------------------------------------
// Spectral attention, fct query only (row-0 mask is all-True).
// Scores phase: each thread owns one j-row, computes ALL 8 heads:
//   xs row read ONCE (16 LDS.128), qW reads are warp-broadcast (cheap).
// ---------------------------------------------------------------------------
__global__ void spectral_kernel(const float* __restrict__ xs,
                                const float* __restrict__ Wqs,
                                const float* __restrict__ Wks,
                                const float* __restrict__ Wvs) {
    __shared__ float xs_s[FF*68];
    __shared__ float q0_s[64];
    __shared__ float qW_s[8*64];
    __shared__ float p_s[8*96];
    __shared__ float a_s[8*64];

    const int bt  = blockIdx.x;
    const int tid = threadIdx.x;   // 256
    const float* xp = xs + (size_t)bt * FF * DSS;

    for (int idx = tid; idx < FF*DSS; idx += 256)
        xs_s[(idx >> 6) * 68 + (idx & 63)] = xp[idx];
    __syncthreads();

    if (tid < 64) {
        float s = 0.f;
        #pragma unroll 8
        for (int k = 0; k < 64; k++) s += xs_s[k] * __ldg(&Wqs[k*64 + tid]);
        q0_s[tid] = s;
    }
    __syncthreads();

    // qW[h][k] = sum_d q0[h*8+d] * Wks[k][h*8+d]
    for (int idx = tid; idx < 512; idx += 256) {
        int h = idx >> 6, k = idx & 63;
        float s = 0.f;
        #pragma unroll
        for (int d = 0; d < 8; d++) s += q0_s[h*8 + d] * __ldg(&Wks[k*64 + h*8 + d]);
        qW_s[idx] = s;
    }
    __syncthreads();

    // ---- scores: thread j computes s[h][j] for all 8 h; xs row read once ----
    const float scale = 0.35355339059327376f;   // 1/sqrt(8)
    if (tid < FF) {
        const int j = tid;
        float acc[8];
        #pragma unroll
        for (int h = 0; h < 8; h++) acc[h] = 0.f;

        #pragma unroll
        for (int c = 0; c < 4; c++) {           // 4 chunks of 16 k
            const float* xr = &xs_s[j*68 + c*16];
            float4 x0 = *(const float4*)(xr);
            float4 x1 = *(const float4*)(xr + 4);
            float4 x2 = *(const float4*)(xr + 8);
            float4 x3 = *(const float4*)(xr + 12);
            #pragma unroll
            for (int h = 0; h < 8; h++) {
                const float* qr = &qW_s[h*64 + c*16];
                float4 w0 = *(const float4*)(qr);
                float4 w1 = *(const float4*)(qr + 4);
                float4 w2 = *(const float4*)(qr + 8);
                float4 w3 = *(const float4*)(qr + 12);
                acc[h] += x0.x*w0.x + x0.y*w0.y + x0.z*w0.z + x0.w*w0.w
                        + x1.x*w1.x + x1.y*w1.y + x1.z*w1.z + x1.w*w1.w
                        + x2.x*w2.x + x2.y*w2.y + x2.z*w2.z + x2.w*w2.w
                        + x3.x*w3.x + x3.y*w3.y + x3.z*w3.z + x3.w*w3.w;
            }
        }
        #pragma unroll
        for (int h = 0; h < 8; h++) p_s[h*96 + j] = acc[h] * scale;
    }
    __syncthreads();

    {
        int w = tid >> 5, lane = tid & 31;
        float m = -3.0e38f;
        for (int j = lane; j < FF; j += 32) m = fmaxf(m, p_s[w*96 + j]);
        #pragma unroll
        for (int o = 16; o > 0; o >>= 1) m = fmaxf(m, __shfl_xor_sync(0xffffffffu, m, o));
        float sum = 0.f;
        for (int j = lane; j < FF; j += 32) {
            float e = __expf(p_s[w*96 + j] - m);
            p_s[w*96 + j] = e; sum += e;
        }
        #pragma unroll
        for (int o = 16; o > 0; o >>= 1) sum += __shfl_xor_sync(0xffffffffu, sum, o);
        float inv = 1.f / sum;
        for (int j = lane; j < FF; j += 32) p_s[w*96 + j] *= inv;
    }
    __syncthreads();

    // a[h][k0..k0+3] = sum_j p[h][j] * xs[j][k0..k0+3]   (128 threads, float4)
    if (tid < 128) {
        const int h = tid >> 4, k4 = (tid & 15) << 2;
        const float* pr = &p_s[h*96];
        float4 acc = make_float4(0.f, 0.f, 0.f, 0.f);
        for (int j = 0; j < FF; j++) {
            float p = pr[j];
            float4 v = *(const float4*)(&xs_s[j*68 + k4]);
            acc.x += p * v.x; acc.y += p * v.y;
            acc.z += p * v.z; acc.w += p * v.w;
        }
        *(float4*)(&a_s[h*64 + k4]) = acc;
    }
    __syncthreads();

    if (tid < 64) {
        int h = tid >> 3;
        float s = 0.f;
        #pragma unroll 8
        for (int k = 0; k < 64; k++) s += a_s[h*64 + k] * __ldg(&Wvs[k*64 + tid]);
        g_y0pre[bt*64 + tid] = s;
    }
}

// ---------------------------------------------------------------------------
// xt = x + y0pre @ WosWt -> tf32 bits (plain layout).
// ---------------------------------------------------------------------------
__global__ void __launch_bounds__(512) xt_kernel(const float* __restrict__ x) {
    const int r0  = blockIdx.x * 16;
    const int tid = threadIdx.x;     // 512
    __shared__ float y0[16][64];

    for (int idx = tid; idx < 16*64; idx += 512)
        y0[idx >> 6][idx & 63] = g_y0pre[(r0 + (idx >> 6)) * 64 + (idx & 63)];
    __syncthreads();

    const int c = tid * 2;
    float2 acc[16];
    #pragma unroll
    for (int r = 0; r < 16; r++)
        acc[r] = *(const float2*)(x + (size_t)(r0 + r) * DD + c);

    #pragma unroll 4
    for (int k = 0; k < 64; k++) {
        float2 w = *(const float2*)(g_WosWt + k * DD + c);
        #pragma unroll
        for (int r = 0; r < 16; r++) {
            float y = y0[r][k];
            acc[r].x += y * w.x; acc[r].y += y * w.y;
        }
    }
    #pragma unroll
    for (int r = 0; r < 16; r++)
        *(uint2*)(g_xt32 + (size_t)(r0 + r) * DD + c) =
            make_uint2(f2tf32(acc[r].x), f2tf32(acc[r].y));
}

// ---------------------------------------------------------------------------
// tf32 tensor-core GEMM, cp.async DOUBLE-BUFFERED, BK=32, ONE sync per tile.
// ---------------------------------------------------------------------------
template <bool CVT_OUT>
__device__ __forceinline__ void gemm_cp_tile(const uint32_t* __restrict__ A32,
                                             const uint32_t* __restrict__ B32,
                                             void* __restrict__ Cv,
                                             int bm, int bn) {
    extern __shared__ uint32_t smdyn[];
    uint32_t* AsBase = smdyn;                        // [2][128][36]
    uint32_t* BsBase = smdyn + 2 * GEMM_AS_STRIDE;   // [2][32][136]

    const int tid  = threadIdx.x;
    const int warp = tid >> 5, lane = tid & 31;
    const int wm = (warp >> 1) * 32;   // 4 warp-rows
    const int wn = (warp & 1) * 64;    // 2 warp-cols
    const int g = lane >> 2, t = lane & 3;

    const int aRow0 = tid >> 3,  aC = (tid & 7) << 2;
    const int bRow0 = tid >> 5,  bC = (tid & 31) << 2;

    auto issue = [&](int k0, int s) {
        uint32_t* As = AsBase + s * GEMM_AS_STRIDE;
        uint32_t* Bs = BsBase + s * GEMM_BS_STRIDE;
        #pragma unroll
        for (int i = 0; i < 4; i++)
            cp16(&As[(aRow0 + 32*i) * 36 + aC],
                 A32 + (size_t)(bm + aRow0 + 32*i) * 1024 + k0 + aC);
        #pragma unroll
        for (int i = 0; i < 4; i++)
            cp16(&Bs[(bRow0 + 8*i) * 136 + bC],
                 B32 + (size_t)(k0 + bRow0 + 8*i) * 1024 + bn + bC);
        cp_commit();
    };

    float acc[2][8][4];
    #pragma unroll
    for (int mi = 0; mi < 2; mi++)
        #pragma unroll
        for (int ni = 0; ni < 8; ni++)
            #pragma unroll
            for (int r = 0; r < 4; r++) acc[mi][ni][r] = 0.f;

    issue(0, 0);

    for (int kt = 0; kt < 32; kt++) {
        const int s = kt & 1;
        cp_wait_all();
        __syncthreads();
        if (kt + 1 < 32) issue((kt + 1) * 32, s ^ 1);

        const uint32_t* As = AsBase + s * GEMM_AS_STRIDE;
        const uint32_t* Bs = BsBase + s * GEMM_BS_STRIDE;
        #pragma unroll
        for (int kk = 0; kk < 32; kk += 8) {
            uint32_t a[2][4], b[8][2];
            #pragma unroll
            for (int mi = 0; mi < 2; mi++) {
                int m = wm + mi * 16 + g;
                a[mi][0] = As[m * 36 + kk + t];
                a[mi][1] = As[(m + 8) * 36 + kk + t];
                a[mi][2] = As[m * 36 + kk + t + 4];
                a[mi][3] = As[(m + 8) * 36 + kk + t + 4];
            }
            #pragma unroll
            for (int ni = 0; ni < 8; ni++) {
                int n = wn + ni * 8 + g;
                b[ni][0] = Bs[(kk + t) * 136 + n];
                b[ni][1] = Bs[(kk + t + 4) * 136 + n];
            }
            #pragma unroll
            for (int mi = 0; mi < 2; mi++)
                #pragma unroll
                for (int ni = 0; ni < 8; ni++)
                    mma_tf32(acc[mi][ni], a[mi], b[ni]);
        }
    }

    #pragma unroll
    for (int mi = 0; mi < 2; mi++) {
        int row0 = bm + wm + mi * 16 + g;
        #pragma unroll
        for (int ni = 0; ni < 8; ni++) {
            int col = bn + wn + ni * 8 + t * 2;
            if (CVT_OUT) {
                uint32_t* C = (uint32_t*)Cv;
                *(uint2*)(C + (size_t)row0 * 1024 + col) =
                    make_uint2(f2tf32(acc[mi][ni][0]), f2tf32(acc[mi][ni][1]));
                *(uint2*)(C + (size_t)(row0 + 8) * 1024 + col) =
                    make_uint2(f2tf32(acc[mi][ni][2]), f2tf32(acc[mi][ni][3]));
            } else {
                float* C = (float*)Cv;
                *(float2*)(C + (size_t)row0 * 1024 + col) =
                    make_float2(acc[mi][ni][0], acc[mi][ni][1]);
                *(float2*)(C + (size_t)(row0 + 8) * 1024 + col) =
                    make_float2(acc[mi][ni][2], acc[mi][ni][3]);
            }
        }
    }
}

__global__ void __launch_bounds__(256, 2) qkv_gemm_kernel() {
    int which = blockIdx.x >> 3;                // 0..2
    int bn    = (blockIdx.x & 7) * 128;
    int bm    = blockIdx.y * 128;
    const uint32_t* W = g_w32 + (size_t)which * DD * DD;
    uint32_t* C = g_qkv32 + (size_t)which * MM * DD;
    gemm_cp_tile<true>(g_xt32, W, C, bm, bn);
}

__global__ void __launch_bounds__(256, 2) out_gemm_kernel(float* __restrict__ C) {
    gemm_cp_tile<false>(g_attnout32, g_w32 + 3 * (size_t)DD * DD, C,
                        blockIdx.y * 128, blockIdx.x * 128);
}

// ---------------------------------------------------------------------------
// Temporal attention: block-diagonal flash on tf32 tensor cores.
// ---------------------------------------------------------------------------
__global__ void __launch_bounds__(256) temporal_attn_kernel(const int* __restrict__ valid_len) {
    __shared__ uint32_t Qs [32][132];
    __shared__ uint32_t KVs[32][132];
    __shared__ float    Ss [32][36];
    __shared__ float m_s[32], l_s[32], al_s[32];
    __shared__ int   lo_s[32], hi_s[32];

    const int qt = blockIdx.x, h = blockIdx.y, b = blockIdx.z;
    const int tid = threadIdx.x;
    const int warp = tid >> 5, lane = tid & 31;
    const int g = lane >> 2, t = lane & 3;
    const int q0 = qt * 32;
    const uint32_t* Q = g_qkv32;
    const uint32_t* K = g_qkv32 + (size_t)MM * DD;
    const uint32_t* V = g_qkv32 + 2 * (size_t)MM * DD;
    const int l = valid_len[b];

    if (tid < 32) {
        int i = q0 + tid;
        int lo, hi;
        const int dv = (h >> 1) + 1;
        if (i < l) {
            int c = (i * dv) / l;
            lo = (c * l + dv - 1) / dv;
            hi = ((c + 1) * l - 1) / dv + 1;
            if (hi > l) hi = l;
        } else { lo = l; hi = TT; }
        lo_s[tid] = lo; hi_s[tid] = hi;
        m_s[tid] = -1e30f; l_s[tid] = 0.f;
    }
    for (int f = tid; f < 32*32; f += 256) {
        int r = f >> 5, c4 = (f & 31) << 2;
        *(uint4*)&Qs[r][c4] =
            *(const uint4*)(Q + (size_t)(b*TT + q0 + r)*DD + h*128 + c4);
    }
    __syncthreads();
    const int bLo = lo_s[0], bHi = hi_s[31];   // lo/hi monotone in i

    const int wmS = (warp >> 2) * 16, wnS = (warp & 3) * 8;   // S: 16x8 per warp
    const int wmP = (warp >> 2) * 16, wnP = (warp & 3) * 32;  // PV: 16x32 per warp
    const float scale = 0.08838834764831845f;  // 1/sqrt(128)

    float O[4][4];
    #pragma unroll
    for (int ni = 0; ni < 4; ni++)
        #pragma unroll
        for (int r = 0; r < 4; r++) O[ni][r] = 0.f;

    for (int kt = bLo & ~31; kt < bHi; kt += 32) {
        for (int f = tid; f < 32*32; f += 256) {
            int r = f >> 5, c4 = (f & 31) << 2;
            int j = kt + r; if (j > TT - 1) j = TT - 1;
            *(uint4*)&KVs[r][c4] =
                *(const uint4*)(K + (size_t)(b*TT + j)*DD + h*128 + c4);
        }
        __syncthreads();

        float sc[4] = {0.f, 0.f, 0.f, 0.f};
        #pragma unroll
        for (int kk = 0; kk < 128; kk += 8) {
            uint32_t a[4], bb[2];
            a[0] = Qs[wmS + g    ][kk + t];
            a[1] = Qs[wmS + g + 8][kk + t];
            a[2] = Qs[wmS + g    ][kk + t + 4];
            a[3] = Qs[wmS + g + 8][kk + t + 4];
            bb[0] = KVs[wnS + g][kk + t];
            bb[1] = KVs[wnS + g][kk + t + 4];
            mma_tf32(sc, a, bb);
        }
        Ss[wmS + g    ][wnS + 2*t    ] = sc[0] * scale;
        Ss[wmS + g    ][wnS + 2*t + 1] = sc[1] * scale;
        Ss[wmS + g + 8][wnS + 2*t    ] = sc[2] * scale;
        Ss[wmS + g + 8][wnS + 2*t + 1] = sc[3] * scale;
        __syncthreads();

        if (tid < 32) {
            const int lo = lo_s[tid], hi = hi_s[tid];
            float mo = m_s[tid];
            float rmax = -3e38f;
            #pragma unroll 8
            for (int j = 0; j < 32; j++) {
                int jg = kt + j;
                float s = (jg >= lo && jg < hi) ? Ss[tid][j] : -3e38f;
                Ss[tid][j] = s;
                rmax = fmaxf(rmax, s);
            }
            float mn = fmaxf(mo, rmax);
            float alpha = __expf(mo - mn);
            float rs = 0.f;
            #pragma unroll 8
            for (int j = 0; j < 32; j++) {
                float p = __expf(Ss[tid][j] - mn);
                Ss[tid][j] = p;
                rs += p;
            }
            l_s[tid] = l_s[tid] * alpha + rs;
            m_s[tid] = mn;
            al_s[tid] = alpha;
        }
        for (int f = tid; f < 32*32; f += 256) {
            int r = f >> 5, c4 = (f & 31) << 2;
            int j = kt + r; if (j > TT - 1) j = TT - 1;
            *(uint4*)&KVs[r][c4] =
                *(const uint4*)(V + (size_t)(b*TT + j)*DD + h*128 + c4);
        }
        __syncthreads();

        {
            float a0 = al_s[wmP + g], a1 = al_s[wmP + g + 8];
            #pragma unroll
            for (int ni = 0; ni < 4; ni++) {
                O[ni][0] *= a0; O[ni][1] *= a0;
                O[ni][2] *= a1; O[ni][3] *= a1;
            }
        }
        #pragma unroll
        for (int kk = 0; kk < 32; kk += 8) {
            uint32_t a[4];
            a[0] = f2tf32(Ss[wmP + g    ][kk + t]);
            a[1] = f2tf32(Ss[wmP + g + 8][kk + t]);
            a[2] = f2tf32(Ss[wmP + g    ][kk + t + 4]);
            a[3] = f2tf32(Ss[wmP + g + 8][kk + t + 4]);
            #pragma unroll
            for (int ni = 0; ni < 4; ni++) {
                uint32_t bb[2];
                int n = wnP + ni * 8 + g;
                bb[0] = KVs[kk + t    ][n];
                bb[1] = KVs[kk + t + 4][n];
                mma_tf32(O[ni], a, bb);
            }
        }
        __syncthreads();
    }

    {
        float inv0 = 1.f / l_s[wmP + g];
        float inv1 = 1.f / l_s[wmP + g + 8];
        const size_t r0 = (size_t)(b*TT + q0 + wmP + g) * DD;
        const size_t r1 = (size_t)(b*TT + q0 + wmP + g + 8) * DD;
        #pragma unroll
        for (int ni = 0; ni < 4; ni++) {
            int col = h*128 + wnP + ni*8 + 2*t;
            *(uint2*)(g_attnout32 + r0 + col) =
                make_uint2(f2tf32(O[ni][0]*inv0), f2tf32(O[ni][1]*inv0));
            *(uint2*)(g_attnout32 + r1 + col) =
                make_uint2(f2tf32(O[ni][2]*inv1), f2tf32(O[ni][3]*inv1));
        }
    }
}

// ---------------------------------------------------------------------------
extern "C" void kernel_launch(void* const* d_in, const int* in_sizes, int n_in,
                              void* d_out, int out_size) {
    const float* x   = (const float*)d_in[0];
    const float* xs  = (const float*)d_in[1];
    const int*   vl  = (const int*)  d_in[2];
    const float* Wq  = (const float*)d_in[3];
    const float* Wk  = (const float*)d_in[4];
    const float* Wv  = (const float*)d_in[5];
    const float* Wo  = (const float*)d_in[6];
    const float* Wqs = (const float*)d_in[7];
    const float* Wks = (const float*)d_in[8];
    const float* Wvs = (const float*)d_in[9];
    const float* Wos = (const float*)d_in[10];
    const float* Wt  = (const float*)d_in[11];
    float* out = (float*)d_out;

    cudaFuncSetAttribute(qkv_gemm_kernel,
                         cudaFuncAttributeMaxDynamicSharedMemorySize, GEMM_SMEM_BYTES);
    cudaFuncSetAttribute(out_gemm_kernel,
                         cudaFuncAttributeMaxDynamicSharedMemorySize, GEMM_SMEM_BYTES);

    woswt_kernel<<<256, 256>>>(Wos, Wt);                       // 0
    prep_qkvw_kernel<<<dim3(1024, 3), 256>>>(Wq, Wk, Wv);      // 1
    prep_wo_kernel<<<1024, 256>>>(Wo);                         // 2
    spectral_kernel<<<MM, 256>>>(xs, Wqs, Wks, Wvs);           // 3  <- ncu capture slot
    xt_kernel<<<MM/16, 512>>>(x);                              // 4
    qkv_gemm_kernel<<<dim3(24, 16), 256, GEMM_SMEM_BYTES>>>(); // 5
    temporal_attn_kernel<<<dim3(TT/32, HH, BB), 256>>>(vl);    // 6
    out_gemm_kernel<<<dim3(8, 16), 256, GEMM_SMEM_BYTES>>>(out); // 7
}

// round 16
// speedup vs baseline: 1.1638x; 1.0220x over previous
#include <cuda_runtime.h>
#include <cstdint>

// Shapes (fixed by the problem)
#define BB   4
#define TT   512
#define FF   93
#define DSS  64
#define DD   1024
#define HH   8
#define MM   (BB*TT)      // 2048 rows

// Scratch (static device allocations; no cudaMalloc allowed)
__device__ float    g_y0pre[MM*DSS];      // spectral fct output pre-Wos  [2048,64]
__device__ float    g_WosWt[DSS*DD];      // Wos @ Wt                     [64,1024]
__device__ uint32_t g_xt32[MM*DD];        // temporal input, tf32 bits (plain [m][k])
__device__ uint32_t g_w32[4*DD*DD];       // Wq,Wk,Wv,Wo tf32 bits (plain [k][n])
__device__ uint32_t g_qkv32[3*MM*DD];     // Q,K,V as tf32 bit patterns
__device__ uint32_t g_attnout32[MM*DD];   // attention out, tf32 bits (plain [m][k])

// GEMM dynamic smem: 2 stages of (As[128][36] + Bs[32][136]) uint32
#define GEMM_AS_STRIDE (128*36)
#define GEMM_BS_STRIDE (32*136)
#define GEMM_SMEM_BYTES ((2*(GEMM_AS_STRIDE + GEMM_BS_STRIDE)) * 4)

// ---------------------------------------------------------------------------
// helpers: tf32 convert + mma + cp.async
// ---------------------------------------------------------------------------
__device__ __forceinline__ uint32_t f2tf32(float x) {
    uint32_t r;
    asm("cvt.rna.tf32.f32 %0, %1;" : "=r"(r) : "f"(x));
    return r;
}
__device__ __forceinline__ void mma_tf32(float c[4], const uint32_t a[4], const uint32_t b[2]) {
    asm volatile(
        "mma.sync.aligned.m16n8k8.row.col.f32.tf32.tf32.f32 "
        "{%0,%1,%2,%3}, {%4,%5,%6,%7}, {%8,%9}, {%0,%1,%2,%3};"
        : "+f"(c[0]), "+f"(c[1]), "+f"(c[2]), "+f"(c[3])
        : "r"(a[0]), "r"(a[1]), "r"(a[2]), "r"(a[3]), "r"(b[0]), "r"(b[1]));
}
__device__ __forceinline__ void cp16(void* dst_smem, const void* src) {
    uint32_t d = (uint32_t)__cvta_generic_to_shared(dst_smem);
    asm volatile("cp.async.cg.shared.global [%0], [%1], 16;" :: "r"(d), "l"(src));
}
__device__ __forceinline__ void cp_commit() {
    asm volatile("cp.async.commit_group;");
}
__device__ __forceinline__ void cp_wait_all() {
    asm volatile("cp.async.wait_group 0;");
}

// ---------------------------------------------------------------------------
// prep: convert weights to tf32 bits (split so spectral lands at launch #3)
// ---------------------------------------------------------------------------
__global__ void prep_qkvw_kernel(const float* __restrict__ Wq,
                                 const float* __restrict__ Wk,
                                 const float* __restrict__ Wv) {
    const int z = blockIdx.y;
    const float* S = (z == 0) ? Wq : (z == 1) ? Wk : Wv;
    int i = (blockIdx.x * 256 + threadIdx.x) * 4;
    float4 v = *(const float4*)(S + i);
    *(uint4*)(g_w32 + (size_t)z * DD * DD + i) =
        make_uint4(f2tf32(v.x), f2tf32(v.y), f2tf32(v.z), f2tf32(v.w));
}
__global__ void prep_wo_kernel(const float* __restrict__ Wo) {
    int i = (blockIdx.x * 256 + threadIdx.x) * 4;
    float4 v = *(const float4*)(Wo + i);
    *(uint4*)(g_w32 + 3 * (size_t)DD * DD + i) =
        make_uint4(f2tf32(v.x), f2tf32(v.y), f2tf32(v.z), f2tf32(v.w));
}

// ---------------------------------------------------------------------------
// WosWt = Wos[64,64] @ Wt[64,1024]
// ---------------------------------------------------------------------------
__global__ void woswt_kernel(const float* __restrict__ Wos, const float* __restrict__ Wt) {
    int idx = blockIdx.x * 256 + threadIdx.x;   // 65536 outputs
    int r = idx >> 10, c = idx & 1023;
    float s = 0.f;
    #pragma unroll 8
    for (int k = 0; k < 64; k++) s += Wos[r*64 + k] * Wt[k*1024 + c];
    g_WosWt[idx] = s;
}

// ---------------------------------------------------------------------------
// Spectral attention, fct query only (row-0 mask is all-True).
// Scores and a-phase on tf32 tensor cores:
//   S[96(93),8] = xs @ qWt   (warps 0..5, one m16 tile each, 8 k-steps)
//   a[16(8),64] = p @ xs     (8 warps, one n8 tile each, 12 k-steps)
// xs_s holds tf32 bits (96 rows, stride 68); p_s stride 100, 16 rows.
// Pad cols of p (93..95) zeroed after softmax; garbage output rows unstored.
// ---------------------------------------------------------------------------
__global__ void spectral_kernel(const float* __restrict__ xs,
                                const float* __restrict__ Wqs,
                                const float* __restrict__ Wks,
                                const float* __restrict__ Wvs) {
    __shared__ uint32_t xs_s[96*68];    // tf32 bits; rows 93..95 garbage pad
    __shared__ float    q0_s[64];
    __shared__ uint32_t qWt_s[64*8];    // [k][h] tf32 bits
    __shared__ uint32_t p_s[16*100];    // rows 0..7 = scores/probs; 8..15 scratch pad
    __shared__ float    a_s[8*64];

    const int bt  = blockIdx.x;
    const int tid = threadIdx.x;   // 256
    const int warp = tid >> 5, lane = tid & 31;
    const int g = lane >> 2, t = lane & 3;
    const float* xp = xs + (size_t)bt * FF * DSS;

    for (int idx = tid; idx < FF*DSS; idx += 256)
        xs_s[(idx >> 6) * 68 + (idx & 63)] = f2tf32(xp[idx]);
    __syncthreads();

    // q0 = xs[0,:] @ Wqs
    if (tid < 64) {
        float s = 0.f;
        #pragma unroll 8
        for (int k = 0; k < 64; k++)
            s += __uint_as_float(xs_s[k]) * __ldg(&Wqs[k*64 + tid]);
        q0_s[tid] = s;
    }
    __syncthreads();

    // qWt[k][h] = sum_d q0[h*8+d] * Wks[k][h*8+d]   (transposed, tf32 bits)
    for (int idx = tid; idx < 512; idx += 256) {
        int h = idx >> 6, k = idx & 63;
        float s = 0.f;
        #pragma unroll
        for (int d = 0; d < 8; d++) s += q0_s[h*8 + d] * __ldg(&Wks[k*64 + h*8 + d]);
        qWt_s[k*8 + h] = f2tf32(s);
    }
    __syncthreads();

    // ---- scores via mma: warps 0..5, rows m0..m0+15, all 8 heads ----
    if (warp < 6) {
        const int m0 = warp * 16;
        float c[4] = {0.f, 0.f, 0.f, 0.f};
        #pragma unroll
        for (int kk = 0; kk < 64; kk += 8) {
            uint32_t a[4], b[2];
            a[0] = xs_s[(m0 + g    ) * 68 + kk + t];
            a[1] = xs_s[(m0 + g + 8) * 68 + kk + t];
            a[2] = xs_s[(m0 + g    ) * 68 + kk + t + 4];
            a[3] = xs_s[(m0 + g + 8) * 68 + kk + t + 4];
            b[0] = qWt_s[(kk + t    ) * 8 + g];
            b[1] = qWt_s[(kk + t + 4) * 8 + g];
            mma_tf32(c, a, b);
        }
        // store raw scores (float bits) into p_s[h][j]
        p_s[(2*t    ) * 100 + m0 + g    ] = __float_as_uint(c[0]);
        p_s[(2*t + 1) * 100 + m0 + g    ] = __float_as_uint(c[1]);
        p_s[(2*t    ) * 100 + m0 + g + 8] = __float_as_uint(c[2]);
        p_s[(2*t + 1) * 100 + m0 + g + 8] = __float_as_uint(c[3]);
    }
    __syncthreads();

    // ---- softmax per head (warp = head); writes tf32-bit probs ----
    {
        const float scale = 0.35355339059327376f;   // 1/sqrt(8)
        float m = -3.0e38f;
        for (int j = lane; j < FF; j += 32)
            m = fmaxf(m, __uint_as_float(p_s[warp*100 + j]) * scale);
        #pragma unroll
        for (int o = 16; o > 0; o >>= 1) m = fmaxf(m, __shfl_xor_sync(0xffffffffu, m, o));
        float sum = 0.f;
        for (int j = lane; j < FF; j += 32) {
            float e = __expf(__uint_as_float(p_s[warp*100 + j]) * scale - m);
            p_s[warp*100 + j] = __float_as_uint(e);
            sum += e;
        }
        #pragma unroll
        for (int o = 16; o > 0; o >>= 1) sum += __shfl_xor_sync(0xffffffffu, sum, o);
        float inv = 1.f / sum;
        for (int j = lane; j < FF; j += 32)
            p_s[warp*100 + j] = f2tf32(__uint_as_float(p_s[warp*100 + j]) * inv);
        if (lane < 3) p_s[warp*100 + FF + lane] = 0;   // zero K-pad cols 93..95
    }
    __syncthreads();

    // ---- a via mma: warp owns n-tile n0..n0+7; K=96 ----
    {
        const int n0 = warp * 8;
        float c[4] = {0.f, 0.f, 0.f, 0.f};
        #pragma unroll
        for (int kk = 0; kk < 96; kk += 8) {
            uint32_t a[4], b[2];
            a[0] = p_s[(g    ) * 100 + kk + t];
            a[1] = p_s[(g + 8) * 100 + kk + t];      // garbage row (discarded)
            a[2] = p_s[(g    ) * 100 + kk + t + 4];
            a[3] = p_s[(g + 8) * 100 + kk + t + 4];  // garbage row (discarded)
            b[0] = xs_s[(kk + t    ) * 68 + n0 + g];
            b[1] = xs_s[(kk + t + 4) * 68 + n0 + g];
            mma_tf32(c, a, b);
        }
        a_s[g * 64 + n0 + 2*t    ] = c[0];
        a_s[g * 64 + n0 + 2*t + 1] = c[1];
        // c[2], c[3] belong to pad rows 8..15 — not stored
    }
    __syncthreads();

    // out0[c] = sum_k a[h][k] * Wvs[k][c],  h = c>>3
    if (tid < 64) {
        int h = tid >> 3;
        float s = 0.f;
        #pragma unroll 8
        for (int k = 0; k < 64; k++) s += a_s[h*64 + k] * __ldg(&Wvs[k*64 + tid]);
        g_y0pre[bt*64 + tid] = s;
    }
}

// ---------------------------------------------------------------------------
// xt = x + y0pre @ WosWt -> tf32 bits (plain layout).
// ---------------------------------------------------------------------------
__global__ void __launch_bounds__(512) xt_kernel(const float* __restrict__ x) {
    const int r0  = blockIdx.x * 16;
    const int tid = threadIdx.x;     // 512
    __shared__ float y0[16][64];

    for (int idx = tid; idx < 16*64; idx += 512)
        y0[idx >> 6][idx & 63] = g_y0pre[(r0 + (idx >> 6)) * 64 + (idx & 63)];
    __syncthreads();

    const int c = tid * 2;
    float2 acc[16];
    #pragma unroll
    for (int r = 0; r < 16; r++)
        acc[r] = *(const float2*)(x + (size_t)(r0 + r) * DD + c);

    #pragma unroll 4
    for (int k = 0; k < 64; k++) {
        float2 w = *(const float2*)(g_WosWt + k * DD + c);
        #pragma unroll
        for (int r = 0; r < 16; r++) {
            float y = y0[r][k];
            acc[r].x += y * w.x; acc[r].y += y * w.y;
        }
    }
    #pragma unroll
    for (int r = 0; r < 16; r++)
        *(uint2*)(g_xt32 + (size_t)(r0 + r) * DD + c) =
            make_uint2(f2tf32(acc[r].x), f2tf32(acc[r].y));
}

// ---------------------------------------------------------------------------
// tf32 tensor-core GEMM, cp.async DOUBLE-BUFFERED, BK=32, ONE sync per tile.
// ---------------------------------------------------------------------------
template <bool CVT_OUT>
__device__ __forceinline__ void gemm_cp_tile(const uint32_t* __restrict__ A32,
                                             const uint32_t* __restrict__ B32,
                                             void* __restrict__ Cv,
                                             int bm, int bn) {
    extern __shared__ uint32_t smdyn[];
    uint32_t* AsBase = smdyn;                        // [2][128][36]
    uint32_t* BsBase = smdyn + 2 * GEMM_AS_STRIDE;   // [2][32][136]

    const int tid  = threadIdx.x;
    const int warp = tid >> 5, lane = tid & 31;
    const int wm = (warp >> 1) * 32;   // 4 warp-rows
    const int wn = (warp & 1) * 64;    // 2 warp-cols
    const int g = lane >> 2, t = lane & 3;

    const int aRow0 = tid >> 3,  aC = (tid & 7) << 2;
    const int bRow0 = tid >> 5,  bC = (tid & 31) << 2;

    auto issue = [&](int k0, int s) {
        uint32_t* As = AsBase + s * GEMM_AS_STRIDE;
        uint32_t* Bs = BsBase + s * GEMM_BS_STRIDE;
        #pragma unroll
        for (int i = 0; i < 4; i++)
            cp16(&As[(aRow0 + 32*i) * 36 + aC],
                 A32 + (size_t)(bm + aRow0 + 32*i) * 1024 + k0 + aC);
        #pragma unroll
        for (int i = 0; i < 4; i++)
            cp16(&Bs[(bRow0 + 8*i) * 136 + bC],
                 B32 + (size_t)(k0 + bRow0 + 8*i) * 1024 + bn + bC);
        cp_commit();
    };

    float acc[2][8][4];
    #pragma unroll
    for (int mi = 0; mi < 2; mi++)
        #pragma unroll
        for (int ni = 0; ni < 8; ni++)
            #pragma unroll
            for (int r = 0; r < 4; r++) acc[mi][ni][r] = 0.f;

    issue(0, 0);

    for (int kt = 0; kt < 32; kt++) {
        const int s = kt & 1;
        cp_wait_all();
        __syncthreads();
        if (kt + 1 < 32) issue((kt + 1) * 32, s ^ 1);

        const uint32_t* As = AsBase + s * GEMM_AS_STRIDE;
        const uint32_t* Bs = BsBase + s * GEMM_BS_STRIDE;
        #pragma unroll
        for (int kk = 0; kk < 32; kk += 8) {
            uint32_t a[2][4], b[8][2];
            #pragma unroll
            for (int mi = 0; mi < 2; mi++) {
                int m = wm + mi * 16 + g;
                a[mi][0] = As[m * 36 + kk + t];
                a[mi][1] = As[(m + 8) * 36 + kk + t];
                a[mi][2] = As[m * 36 + kk + t + 4];
                a[mi][3] = As[(m + 8) * 36 + kk + t + 4];
            }
            #pragma unroll
            for (int ni = 0; ni < 8; ni++) {
                int n = wn + ni * 8 + g;
                b[ni][0] = Bs[(kk + t) * 136 + n];
                b[ni][1] = Bs[(kk + t + 4) * 136 + n];
            }
            #pragma unroll
            for (int mi = 0; mi < 2; mi++)
                #pragma unroll
                for (int ni = 0; ni < 8; ni++)
                    mma_tf32(acc[mi][ni], a[mi], b[ni]);
        }
    }

    #pragma unroll
    for (int mi = 0; mi < 2; mi++) {
        int row0 = bm + wm + mi * 16 + g;
        #pragma unroll
        for (int ni = 0; ni < 8; ni++) {
            int col = bn + wn + ni * 8 + t * 2;
            if (CVT_OUT) {
                uint32_t* C = (uint32_t*)Cv;
                *(uint2*)(C + (size_t)row0 * 1024 + col) =
                    make_uint2(f2tf32(acc[mi][ni][0]), f2tf32(acc[mi][ni][1]));
                *(uint2*)(C + (size_t)(row0 + 8) * 1024 + col) =
                    make_uint2(f2tf32(acc[mi][ni][2]), f2tf32(acc[mi][ni][3]));
            } else {
                float* C = (float*)Cv;
                *(float2*)(C + (size_t)row0 * 1024 + col) =
                    make_float2(acc[mi][ni][0], acc[mi][ni][1]);
                *(float2*)(C + (size_t)(row0 + 8) * 1024 + col) =
                    make_float2(acc[mi][ni][2], acc[mi][ni][3]);
            }
        }
    }
}

__global__ void __launch_bounds__(256, 2) qkv_gemm_kernel() {
    int which = blockIdx.x >> 3;                // 0..2
    int bn    = (blockIdx.x & 7) * 128;
    int bm    = blockIdx.y * 128;
    const uint32_t* W = g_w32 + (size_t)which * DD * DD;
    uint32_t* C = g_qkv32 + (size_t)which * MM * DD;
    gemm_cp_tile<true>(g_xt32, W, C, bm, bn);
}

__global__ void __launch_bounds__(256, 2) out_gemm_kernel(float* __restrict__ C) {
    gemm_cp_tile<false>(g_attnout32, g_w32 + 3 * (size_t)DD * DD, C,
                        blockIdx.y * 128, blockIdx.x * 128);
}

// ---------------------------------------------------------------------------
// Temporal attention: block-diagonal flash on tf32 tensor cores.
// ---------------------------------------------------------------------------
__global__ void __launch_bounds__(256) temporal_attn_kernel(const int* __restrict__ valid_len) {
    __shared__ uint32_t Qs [32][132];
    __shared__ uint32_t KVs[32][132];
    __shared__ float    Ss [32][36];
    __shared__ float m_s[32], l_s[32], al_s[32];
    __shared__ int   lo_s[32], hi_s[32];

    const int qt = blockIdx.x, h = blockIdx.y, b = blockIdx.z;
    const int tid = threadIdx.x;
    const int warp = tid >> 5, lane = tid & 31;
    const int g = lane >> 2, t = lane & 3;
    const int q0 = qt * 32;
    const uint32_t* Q = g_qkv32;
    const uint32_t* K = g_qkv32 + (size_t)MM * DD;
    const uint32_t* V = g_qkv32 + 2 * (size_t)MM * DD;
    const int l = valid_len[b];

    if (tid < 32) {
        int i = q0 + tid;
        int lo, hi;
        const int dv = (h >> 1) + 1;
        if (i < l) {
            int c = (i * dv) / l;
            lo = (c * l + dv - 1) / dv;
            hi = ((c + 1) * l - 1) / dv + 1;
            if (hi > l) hi = l;
        } else { lo = l; hi = TT; }
        lo_s[tid] = lo; hi_s[tid] = hi;
        m_s[tid] = -1e30f; l_s[tid] = 0.f;
    }
    for (int f = tid; f < 32*32; f += 256) {
        int r = f >> 5, c4 = (f & 31) << 2;
        *(uint4*)&Qs[r][c4] =
            *(const uint4*)(Q + (size_t)(b*TT + q0 + r)*DD + h*128 + c4);
    }
    __syncthreads();
    const int bLo = lo_s[0], bHi = hi_s[31];   // lo/hi monotone in i

    const int wmS = (warp >> 2) * 16, wnS = (warp & 3) * 8;   // S: 16x8 per warp
    const int wmP = (warp >> 2) * 16, wnP = (warp & 3) * 32;  // PV: 16x32 per warp
    const float scale = 0.08838834764831845f;  // 1/sqrt(128)

    float O[4][4];
    #pragma unroll
    for (int ni = 0; ni < 4; ni++)
        #pragma unroll
        for (int r = 0; r < 4; r++) O[ni][r] = 0.f;

    for (int kt = bLo & ~31; kt < bHi; kt += 32) {
        for (int f = tid; f < 32*32; f += 256) {
            int r = f >> 5, c4 = (f & 31) << 2;
            int j = kt + r; if (j > TT - 1) j = TT - 1;
            *(uint4*)&KVs[r][c4] =
                *(const uint4*)(K + (size_t)(b*TT + j)*DD + h*128 + c4);
        }
        __syncthreads();

        float sc[4] = {0.f, 0.f, 0.f, 0.f};
        #pragma unroll
        for (int kk = 0; kk < 128; kk += 8) {
            uint32_t a[4], bb[2];
            a[0] = Qs[wmS + g    ][kk + t];
            a[1] = Qs[wmS + g + 8][kk + t];
            a[2] = Qs[wmS + g    ][kk + t + 4];
            a[3] = Qs[wmS + g + 8][kk + t + 4];
            bb[0] = KVs[wnS + g][kk + t];
            bb[1] = KVs[wnS + g][kk + t + 4];
            mma_tf32(sc, a, bb);
        }
        Ss[wmS + g    ][wnS + 2*t    ] = sc[0] * scale;
        Ss[wmS + g    ][wnS + 2*t + 1] = sc[1] * scale;
        Ss[wmS + g + 8][wnS + 2*t    ] = sc[2] * scale;
        Ss[wmS + g + 8][wnS + 2*t + 1] = sc[3] * scale;
        __syncthreads();

        if (tid < 32) {
            const int lo = lo_s[tid], hi = hi_s[tid];
            float mo = m_s[tid];
            float rmax = -3e38f;
            #pragma unroll 8
            for (int j = 0; j < 32; j++) {
                int jg = kt + j;
                float s = (jg >= lo && jg < hi) ? Ss[tid][j] : -3e38f;
                Ss[tid][j] = s;
                rmax = fmaxf(rmax, s);
            }
            float mn = fmaxf(mo, rmax);
            float alpha = __expf(mo - mn);
            float rs = 0.f;
            #pragma unroll 8
            for (int j = 0; j < 32; j++) {
                float p = __expf(Ss[tid][j] - mn);
                Ss[tid][j] = p;
                rs += p;
            }
            l_s[tid] = l_s[tid] * alpha + rs;
            m_s[tid] = mn;
            al_s[tid] = alpha;
        }
        for (int f = tid; f < 32*32; f += 256) {
            int r = f >> 5, c4 = (f & 31) << 2;
            int j = kt + r; if (j > TT - 1) j = TT - 1;
            *(uint4*)&KVs[r][c4] =
                *(const uint4*)(V + (size_t)(b*TT + j)*DD + h*128 + c4);
        }
        __syncthreads();

        {
            float a0 = al_s[wmP + g], a1 = al_s[wmP + g + 8];
            #pragma unroll
            for (int ni = 0; ni < 4; ni++) {
                O[ni][0] *= a0; O[ni][1] *= a0;
                O[ni][2] *= a1; O[ni][3] *= a1;
            }
        }
        #pragma unroll
        for (int kk = 0; kk < 32; kk += 8) {
            uint32_t a[4];
            a[0] = f2tf32(Ss[wmP + g    ][kk + t]);
            a[1] = f2tf32(Ss[wmP + g + 8][kk + t]);
            a[2] = f2tf32(Ss[wmP + g    ][kk + t + 4]);
            a[3] = f2tf32(Ss[wmP + g + 8][kk + t + 4]);
            #pragma unroll
            for (int ni = 0; ni < 4; ni++) {
                uint32_t bb[2];
                int n = wnP + ni * 8 + g;
                bb[0] = KVs[kk + t    ][n];
                bb[1] = KVs[kk + t + 4][n];
                mma_tf32(O[ni], a, bb);
            }
        }
        __syncthreads();
    }

    {
        float inv0 = 1.f / l_s[wmP + g];
        float inv1 = 1.f / l_s[wmP + g + 8];
        const size_t r0 = (size_t)(b*TT + q0 + wmP + g) * DD;
        const size_t r1 = (size_t)(b*TT + q0 + wmP + g + 8) * DD;
        #pragma unroll
        for (int ni = 0; ni < 4; ni++) {
            int col = h*128 + wnP + ni*8 + 2*t;
            *(uint2*)(g_attnout32 + r0 + col) =
                make_uint2(f2tf32(O[ni][0]*inv0), f2tf32(O[ni][1]*inv0));
            *(uint2*)(g_attnout32 + r1 + col) =
                make_uint2(f2tf32(O[ni][2]*inv1), f2tf32(O[ni][3]*inv1));
        }
    }
}

// ---------------------------------------------------------------------------
extern "C" void kernel_launch(void* const* d_in, const int* in_sizes, int n_in,
                              void* d_out, int out_size) {
    const float* x   = (const float*)d_in[0];
    const float* xs  = (const float*)d_in[1];
    const int*   vl  = (const int*)  d_in[2];
    const float* Wq  = (const float*)d_in[3];
    const float* Wk  = (const float*)d_in[4];
    const float* Wv  = (const float*)d_in[5];
    const float* Wo  = (const float*)d_in[6];
    const float* Wqs = (const float*)d_in[7];
    const float* Wks = (const float*)d_in[8];
    const float* Wvs = (const float*)d_in[9];
    const float* Wos = (const float*)d_in[10];
    const float* Wt  = (const float*)d_in[11];
    float* out = (float*)d_out;

    cudaFuncSetAttribute(qkv_gemm_kernel,
                         cudaFuncAttributeMaxDynamicSharedMemorySize, GEMM_SMEM_BYTES);
    cudaFuncSetAttribute(out_gemm_kernel,
                         cudaFuncAttributeMaxDynamicSharedMemorySize, GEMM_SMEM_BYTES);

    woswt_kernel<<<256, 256>>>(Wos, Wt);                       // 0
    prep_qkvw_kernel<<<dim3(1024, 3), 256>>>(Wq, Wk, Wv);      // 1
    prep_wo_kernel<<<1024, 256>>>(Wo);                         // 2
    spectral_kernel<<<MM, 256>>>(xs, Wqs, Wks, Wvs);           // 3  <- ncu capture slot
    xt_kernel<<<MM/16, 512>>>(x);                              // 4
    qkv_gemm_kernel<<<dim3(24, 16), 256, GEMM_SMEM_BYTES>>>(); // 5
    temporal_attn_kernel<<<dim3(TT/32, HH, BB), 256>>>(vl);    // 6
    out_gemm_kernel<<<dim3(8, 16), 256, GEMM_SMEM_BYTES>>>(out); // 7
}